// round 1
// baseline (speedup 1.0000x reference)
#include <cuda_runtime.h>
#include <cuda_bf16.h>
#include <math.h>

// ---------------------------------------------------------------------------
// Problem constants
//   xq: (Nq=64, M=16, B=8, C=512), xk/xv: (B=8, K=256, C=512)
//   out = concat( x:(64,16,8,512) = 4194304 floats, score:(8,256,16,64) = 2097152 floats )
// ---------------------------------------------------------------------------
#define NQ   64
#define MM   16
#define BB   8
#define KK   256
#define CC   512
#define NROWS_Q (NQ*MM*BB)      // 8192
#define NROWS_K (BB*KK)         // 2048
#define BKP     (BB*KK)         // 2048 sinkhorn problems
#define EPS_OT  0.05f
#define INV_EPS 20.0f
#define X_ELEMS (NROWS_Q*CC)    // 4194304

// Scratch (device globals; no allocation allowed)
__device__ float g_qlin[NROWS_Q*CC];
__device__ float g_qr  [NROWS_Q*CC];
__device__ float g_klin[NROWS_K*CC];
__device__ float g_v   [NROWS_K*CC];
__device__ float g_sim [BKP*MM*NQ];
__device__ float g_T   [BKP*MM*NQ];
__device__ float g_y   [NROWS_Q*CC];

// ---------------------------------------------------------------------------
// SGEMM: C[m][n] = sum_k Aload(m,k)*Bload(n,k)
//   AT=0: A row-major (m,k)   AT=1: A stored k-major: Aload=A[k*lda+m]
//   BT=0: B row-major (n,k)   BT=1: B stored k-major: Bload=B[k*ldb+n]
//   EPI=0: plain store to C (ldc)
//   EPI=1: out-proj scatter: global row R=b*1024+(mq*64+nq) -> ((nq*16+mq)*8+b), +bias
// Tiles 128x128x8, 256 threads, 8x8 per thread. All dims divisible.
// ---------------------------------------------------------------------------
template<int AT, int BT, int EPI>
__global__ __launch_bounds__(256, 2)
void sgemm_kernel(const float* __restrict__ A, const float* __restrict__ B,
                  float* __restrict__ C, const float* __restrict__ bias,
                  int M, int N, int K, int lda, int ldb, int ldc,
                  int aStride, int bStride, int cStride)
{
    const int bz = blockIdx.z;
    A += (long)bz * aStride;
    B += (long)bz * bStride;
    if (EPI == 0) C += (long)bz * cStride;

    __shared__ float As[8][128];
    __shared__ float Bs[8][128];

    const int tid = threadIdx.x;
    const int mb = blockIdx.y * 128;
    const int nb = blockIdx.x * 128;
    const int tx = tid & 15;
    const int ty = tid >> 4;

    float acc[8][8];
#pragma unroll
    for (int i = 0; i < 8; i++)
#pragma unroll
        for (int j = 0; j < 8; j++) acc[i][j] = 0.f;

    for (int kb = 0; kb < K; kb += 8) {
        // ---- load A tile ----
        if (AT == 0) {
            int r = tid >> 1, c4 = (tid & 1) * 4;
            float4 v = *(const float4*)&A[(long)(mb + r) * lda + kb + c4];
            As[c4 + 0][r] = v.x; As[c4 + 1][r] = v.y;
            As[c4 + 2][r] = v.z; As[c4 + 3][r] = v.w;
        } else {
            int kk2 = tid >> 5, m4 = (tid & 31) * 4;
            *(float4*)&As[kk2][m4] = *(const float4*)&A[(long)(kb + kk2) * lda + mb + m4];
        }
        // ---- load B tile ----
        if (BT == 0) {
            int r = tid >> 1, c4 = (tid & 1) * 4;
            float4 v = *(const float4*)&B[(long)(nb + r) * ldb + kb + c4];
            Bs[c4 + 0][r] = v.x; Bs[c4 + 1][r] = v.y;
            Bs[c4 + 2][r] = v.z; Bs[c4 + 3][r] = v.w;
        } else {
            int kk2 = tid >> 5, n4 = (tid & 31) * 4;
            *(float4*)&Bs[kk2][n4] = *(const float4*)&B[(long)(kb + kk2) * ldb + nb + n4];
        }
        __syncthreads();

#pragma unroll
        for (int k = 0; k < 8; k++) {
            float4 a0 = *(const float4*)&As[k][ty * 8];
            float4 a1 = *(const float4*)&As[k][ty * 8 + 4];
            float4 b0 = *(const float4*)&Bs[k][tx * 8];
            float4 b1 = *(const float4*)&Bs[k][tx * 8 + 4];
            float ar[8] = {a0.x, a0.y, a0.z, a0.w, a1.x, a1.y, a1.z, a1.w};
            float br[8] = {b0.x, b0.y, b0.z, b0.w, b1.x, b1.y, b1.z, b1.w};
#pragma unroll
            for (int i = 0; i < 8; i++)
#pragma unroll
                for (int j = 0; j < 8; j++)
                    acc[i][j] += ar[i] * br[j];
        }
        __syncthreads();
    }

    // ---- epilogue ----
    const int col0 = nb + tx * 8;
    if (EPI == 0) {
#pragma unroll
        for (int i = 0; i < 8; i++) {
            float* crow = C + (long)(mb + ty * 8 + i) * ldc + col0;
            *(float4*)&crow[0] = make_float4(acc[i][0], acc[i][1], acc[i][2], acc[i][3]);
            *(float4*)&crow[4] = make_float4(acc[i][4], acc[i][5], acc[i][6], acc[i][7]);
        }
    } else {
        float4 bz0 = *(const float4*)&bias[col0];
        float4 bz1 = *(const float4*)&bias[col0 + 4];
#pragma unroll
        for (int i = 0; i < 8; i++) {
            int R  = mb + ty * 8 + i;         // = b*1024 + mq*64 + nq
            int bb2 = R >> 10;
            int j  = R & 1023;
            int mq = j >> 6, nq = j & 63;
            int orow = ((nq << 4) + mq) * 8 + bb2;   // x layout (n,m,b)
            float* crow = C + (long)orow * CC + col0;
            *(float4*)&crow[0] = make_float4(acc[i][0] + bz0.x, acc[i][1] + bz0.y,
                                             acc[i][2] + bz0.z, acc[i][3] + bz0.w);
            *(float4*)&crow[4] = make_float4(acc[i][4] + bz1.x, acc[i][5] + bz1.y,
                                             acc[i][6] + bz1.z, acc[i][7] + bz1.w);
        }
    }
}

// ---------------------------------------------------------------------------
// L2 row normalize (512 cols). REORDER=1: scatter q rows (n,m,b) -> [b][m*64+n]
// ---------------------------------------------------------------------------
template<int REORDER>
__global__ void norm_kernel(const float* __restrict__ in, float* __restrict__ out)
{
    const int r = blockIdx.x;
    const int t = threadIdx.x;          // 128 threads, float4 each
    const float4 v = ((const float4*)(in + (long)r * CC))[t];
    float ss = v.x * v.x + v.y * v.y + v.z * v.z + v.w * v.w;
#pragma unroll
    for (int o = 16; o; o >>= 1) ss += __shfl_xor_sync(0xffffffffu, ss, o);
    __shared__ float sw[4];
    if ((t & 31) == 0) sw[t >> 5] = ss;
    __syncthreads();
    float tot = sw[0] + sw[1] + sw[2] + sw[3];
    float scale = 1.0f / fmaxf(sqrtf(tot), 1e-12f);

    long orow;
    if (REORDER) {
        int n = r >> 7, m = (r >> 3) & 15, b = r & 7;
        orow = (long)(b * 1024 + m * 64 + n);
    } else {
        orow = r;
    }
    float4 o4 = make_float4(v.x * scale, v.y * scale, v.z * scale, v.w * scale);
    ((float4*)(out + orow * CC))[t] = o4;
}

// ---------------------------------------------------------------------------
// Sinkhorn: one warp per (b,k) problem. Scaling form:
//   Ke = exp((sim-1)/eps);  a = mu'/(Ke b);  b = nu'/(Ke^T a)   x100
//   T = a * Ke * b ; score = 1024 * sim * T
// Lane owns columns {lane, lane+32}; rows 0..15 in registers.
// ---------------------------------------------------------------------------
__global__ __launch_bounds__(256)
void sinkhorn_kernel(const float* __restrict__ sim, float* __restrict__ T,
                     float* __restrict__ score)
{
    const int p    = blockIdx.x * 8 + (threadIdx.x >> 5);   // 0..2047
    const int lane = threadIdx.x & 31;
    const float* srow = sim + (long)p * (MM * NQ);

    float Km[32];
#pragma unroll
    for (int i = 0; i < 16; i++) {
        Km[i]      = __expf((srow[i * 64 + lane]      - 1.0f) * INV_EPS);
        Km[i + 16] = __expf((srow[i * 64 + lane + 32] - 1.0f) * INV_EPS);
    }

    const float MU = 1.0f / 16.0f + 1e-8f;
    const float NU = 1.0f / 64.0f + 1e-8f;
    float b0 = 1.0f, b1 = 1.0f;
    float a[16];

#pragma unroll 1
    for (int iter = 0; iter < 100; iter++) {
        // ---- row sums S_i = sum_j Ke_ij * b_j ----
        float v[16];
#pragma unroll
        for (int i = 0; i < 16; i++) v[i] = Km[i] * b0 + Km[i + 16] * b1;
        // fold upper 16 lanes
#pragma unroll
        for (int i = 0; i < 16; i++) v[i] += __shfl_xor_sync(0xffffffffu, v[i], 16);
        // register-halving tree: lane ends with S_{lane&15} in v[0]
#pragma unroll
        for (int i = 0; i < 8; i++) {
            float t0 = v[i], t1 = v[i + 8];
            float r0 = __shfl_xor_sync(0xffffffffu, t0, 8);
            float r1 = __shfl_xor_sync(0xffffffffu, t1, 8);
            v[i] = (lane & 8) ? (t1 + r1) : (t0 + r0);
        }
#pragma unroll
        for (int i = 0; i < 4; i++) {
            float t0 = v[i], t1 = v[i + 4];
            float r0 = __shfl_xor_sync(0xffffffffu, t0, 4);
            float r1 = __shfl_xor_sync(0xffffffffu, t1, 4);
            v[i] = (lane & 4) ? (t1 + r1) : (t0 + r0);
        }
#pragma unroll
        for (int i = 0; i < 2; i++) {
            float t0 = v[i], t1 = v[i + 2];
            float r0 = __shfl_xor_sync(0xffffffffu, t0, 2);
            float r1 = __shfl_xor_sync(0xffffffffu, t1, 2);
            v[i] = (lane & 2) ? (t1 + r1) : (t0 + r0);
        }
        {
            float t0 = v[0], t1 = v[1];
            float r0 = __shfl_xor_sync(0xffffffffu, t0, 1);
            float r1 = __shfl_xor_sync(0xffffffffu, t1, 1);
            v[0] = (lane & 1) ? (t1 + r1) : (t0 + r0);
        }
        // a_i = mu'/S_i ; broadcast
        float av = __fdividef(MU, v[0]);
#pragma unroll
        for (int i = 0; i < 16; i++) a[i] = __shfl_sync(0xffffffffu, av, i);

        // ---- column sums t_j = sum_i Ke_ij * a_i (lane-local) ----
        float c0a = 0.f, c0b = 0.f, c1a = 0.f, c1b = 0.f;
#pragma unroll
        for (int i = 0; i < 16; i += 2) {
            c0a += Km[i] * a[i];       c0b += Km[i + 1] * a[i + 1];
            c1a += Km[i + 16] * a[i];  c1b += Km[i + 17] * a[i + 1];
        }
        b0 = __fdividef(NU, c0a + c0b);
        b1 = __fdividef(NU, c1a + c1b);
    }

    // ---- T and score ----
    float* Trow = T + (long)p * (MM * NQ);
    float* Srow = score + (long)p * (MM * NQ);
#pragma unroll
    for (int i = 0; i < 16; i++) {
        float T0 = a[i] * Km[i] * b0;
        float T1 = a[i] * Km[i + 16] * b1;
        Trow[i * 64 + lane]      = T0;
        Trow[i * 64 + lane + 32] = T1;
        Srow[i * 64 + lane]      = 1024.0f * srow[i * 64 + lane] * T0;
        Srow[i * 64 + lane + 32] = 1024.0f * srow[i * 64 + lane + 32] * T1;
    }
}

// ---------------------------------------------------------------------------
extern "C" void kernel_launch(void* const* d_in, const int* in_sizes, int n_in,
                              void* d_out, int out_size)
{
    const float* xq = (const float*)d_in[0];
    const float* xk = (const float*)d_in[1];
    const float* xv = (const float*)d_in[2];
    const float* Wq = (const float*)d_in[3];
    const float* Wk = (const float*)d_in[4];
    const float* Wv = (const float*)d_in[5];
    const float* Wp = (const float*)d_in[6];
    const float* bp = (const float*)d_in[7];
    float* out_x     = (float*)d_out;
    float* out_score = out_x + X_ELEMS;

    float *qlin, *qr, *klin, *vbuf, *sim, *T, *y;
    cudaGetSymbolAddress((void**)&qlin, g_qlin);
    cudaGetSymbolAddress((void**)&qr,   g_qr);
    cudaGetSymbolAddress((void**)&klin, g_klin);
    cudaGetSymbolAddress((void**)&vbuf, g_v);
    cudaGetSymbolAddress((void**)&sim,  g_sim);
    cudaGetSymbolAddress((void**)&T,    g_T);
    cudaGetSymbolAddress((void**)&y,    g_y);

    dim3 blk(256);

    // projections: Y = X @ W^T
    sgemm_kernel<0,0,0><<<dim3(CC/128, NROWS_Q/128, 1), blk>>>(
        xq, Wq, qlin, nullptr, NROWS_Q, CC, CC, CC, CC, CC, 0, 0, 0);
    sgemm_kernel<0,0,0><<<dim3(CC/128, NROWS_K/128, 1), blk>>>(
        xk, Wk, klin, nullptr, NROWS_K, CC, CC, CC, CC, CC, 0, 0, 0);
    sgemm_kernel<0,0,0><<<dim3(CC/128, NROWS_K/128, 1), blk>>>(
        xv, Wv, vbuf, nullptr, NROWS_K, CC, CC, CC, CC, CC, 0, 0, 0);

    // l2 normalize (+ reorder q into [b][m*64+n][c])
    norm_kernel<1><<<NROWS_Q, 128>>>(qlin, qr);
    norm_kernel<0><<<NROWS_K, 128>>>(klin, klin);

    // sim[b*256+k][m*64+n] = kk_b[k,:] . qr_b[m*64+n,:]   (batched over b)
    sgemm_kernel<0,0,0><<<dim3(1024/128, KK/128, BB), blk>>>(
        klin, qr, sim, nullptr, KK, 1024, CC, CC, CC, 1024,
        KK * CC, 1024 * CC, KK * 1024);

    // Sinkhorn -> T (natural layout) + score_map
    sinkhorn_kernel<<<BKP/8, 256>>>(sim, T, out_score);

    // y_b[m*64+n][c] = sum_k T_b[k][m*64+n] * v_b[k][c]   (A transposed, B k-major)
    sgemm_kernel<1,1,0><<<dim3(CC/128, 1024/128, BB), blk>>>(
        T, vbuf, y, nullptr, 1024, CC, KK, 1024, CC, CC,
        KK * 1024, KK * CC, 1024 * CC);

    // out-proj + bias + scatter to x layout (n,m,b,c)
    sgemm_kernel<0,0,1><<<dim3(CC/128, NROWS_Q/128, 1), blk>>>(
        y, Wp, out_x, bp, NROWS_Q, CC, CC, CC, CC, CC, 0, 0, 0);
}

// round 3
// speedup vs baseline: 1.7686x; 1.7686x over previous
#include <cuda_runtime.h>
#include <cuda_bf16.h>
#include <cstdint>
#include <math.h>

// ---------------------------------------------------------------------------
// Problem constants
// ---------------------------------------------------------------------------
#define NQ   64
#define MMQ  16
#define BB   8
#define KK   256
#define CC   512
#define K3   1536           // 3*CC for split-bf16 GEMMs
#define NROWS_Q 8192
#define NROWS_K 2048
#define BKP     2048
#define INV_EPS 20.0f
#define X_ELEMS (NROWS_Q*CC)

// ---------------------------------------------------------------------------
// Scratch (device globals; no allocation allowed)
// ---------------------------------------------------------------------------
__device__ __nv_bfloat16 g_xq3[NROWS_Q*K3];
__device__ __nv_bfloat16 g_xk3[NROWS_K*K3];
__device__ __nv_bfloat16 g_xv3[NROWS_K*K3];
__device__ __nv_bfloat16 g_wq3[CC*K3];
__device__ __nv_bfloat16 g_wk3[CC*K3];
__device__ __nv_bfloat16 g_wv3[CC*K3];
__device__ __nv_bfloat16 g_wp3[CC*K3];
__device__ float g_qlin[NROWS_Q*CC];
__device__ float g_klin[NROWS_K*CC];
__device__ float g_v   [NROWS_K*CC];
__device__ __nv_bfloat16 g_qr3[NROWS_Q*K3];
__device__ __nv_bfloat16 g_kn3[NROWS_K*K3];
__device__ float g_sim[BKP*MMQ*NQ];
__device__ float g_T  [BKP*MMQ*NQ];
__device__ __nv_bfloat16 g_Tt3[BB*1024*768];
__device__ __nv_bfloat16 g_vT3[BB*512*768];
__device__ float g_y[NROWS_Q*CC];
__device__ __nv_bfloat16 g_y3[NROWS_Q*K3];

// ---------------------------------------------------------------------------
// PTX helpers
// ---------------------------------------------------------------------------
__device__ __forceinline__ uint32_t s2u(const void* p){
    uint32_t a;
    asm("{ .reg .u64 t; cvta.to.shared.u64 t, %1; cvt.u32.u64 %0, t; }"
        : "=r"(a) : "l"(p));
    return a;
}

#define CP_ASYNC16(dst, src) \
    asm volatile("cp.async.cg.shared.global [%0], [%1], 16;" :: "r"(dst), "l"(src) : "memory")
#define CP_COMMIT() asm volatile("cp.async.commit_group;" ::: "memory")
#define CP_WAIT1()  asm volatile("cp.async.wait_group 1;" ::: "memory")
#define CP_WAIT0()  asm volatile("cp.async.wait_group 0;" ::: "memory")

#define LDMATRIX_X4(r0, r1, r2, r3, addr) \
    asm volatile("ldmatrix.sync.aligned.m8n8.x4.shared.b16 {%0,%1,%2,%3}, [%4];" \
                 : "=r"(r0), "=r"(r1), "=r"(r2), "=r"(r3) : "r"(addr))

#define MMA16816(d, a, b0, b1) \
    asm volatile("mma.sync.aligned.m16n8k16.row.col.f32.bf16.bf16.f32 " \
                 "{%0,%1,%2,%3}, {%4,%5,%6,%7}, {%8,%9}, {%0,%1,%2,%3};" \
                 : "+f"((d)[0]), "+f"((d)[1]), "+f"((d)[2]), "+f"((d)[3]) \
                 : "r"((a)[0]), "r"((a)[1]), "r"((a)[2]), "r"((a)[3]), \
                   "r"(b0), "r"(b1))

__device__ __forceinline__ unsigned short bfr(__nv_bfloat16 h){
    return *reinterpret_cast<unsigned short*>(&h);
}
__device__ __forceinline__ void split_bf16(float x, __nv_bfloat16& h, __nv_bfloat16& l){
    h = __float2bfloat16(x);
    l = __float2bfloat16(x - __bfloat162float(h));
}

// ---------------------------------------------------------------------------
// HMMA GEMM: C[M,N] = A(M,K')·B(N,K')ᵀ, both K-major bf16, fp32 out.
// CTA tile 128x128, BK=64, double-buffered cp.async, 8 warps (4m x 2n),
// warp tile 32x64 via mma.sync.m16n8k16.
// EPI=0 plain store; EPI=1 out-proj scatter + bias.
// Smem per stage: A 16KB + B 16KB; rows are 128B with XOR-16B swizzle.
// ---------------------------------------------------------------------------
#define GSMEM (2*32768)

template<int EPI>
__global__ __launch_bounds__(256)
void hgemm(const __nv_bfloat16* __restrict__ A, const __nv_bfloat16* __restrict__ B,
           float* __restrict__ C, const float* __restrict__ bias,
           int Kp, int ldc, long aStride, long bStride, long cStride)
{
    extern __shared__ char smem[];
    const int bz = blockIdx.z;
    A += bz * aStride;
    B += bz * bStride;
    if (EPI == 0) C += bz * cStride;
    const int mb = blockIdx.y * 128;
    const int nb = blockIdx.x * 128;
    const int tid  = threadIdx.x;
    const int w    = tid >> 5;
    const int lane = tid & 31;
    const int wm   = (w & 3) * 32;      // warp row offset
    const int wn   = (w >> 2) * 64;     // warp col offset

    const uint32_t sbase = s2u(smem);
    const int NC = Kp >> 6;             // chunks of 64

    // cp.async geometry: 2048 16B-chunks per stage (A:1024, B:1024), 8/thread
    const int lrow = tid >> 1;              // 0..127
    const int lcg0 = (tid & 1) * 4;         // first of 4 col-groups (16B units)

    auto load_chunk = [&](int c, int s){
        const uint32_t st = sbase + s * 32768;
        const __nv_bfloat16* Ag = A + (long)(mb + lrow) * Kp + c * 64 + lcg0 * 8;
        const __nv_bfloat16* Bg = B + (long)(nb + lrow) * Kp + c * 64 + lcg0 * 8;
        const uint32_t rbase = lrow * 128;
        const uint32_t sw    = (lrow & 7) << 4;
#pragma unroll
        for (int j = 0; j < 4; j++) {
            uint32_t off = rbase + (((lcg0 + j) << 4) ^ sw);
            CP_ASYNC16(st + off, Ag + j * 8);
            CP_ASYNC16(st + 16384 + off, Bg + j * 8);
        }
        CP_COMMIT();
    };

    float acc[2][8][4];
#pragma unroll
    for (int i = 0; i < 2; i++)
#pragma unroll
        for (int j = 0; j < 8; j++)
#pragma unroll
            for (int q = 0; q < 4; q++) acc[i][j][q] = 0.f;

    load_chunk(0, 0);
    if (NC > 1) load_chunk(1, 1);

    // ldmatrix per-lane address pieces
    const int a_r  = lane & 15;             // row within m16 tile
    const int a_kb = (lane & 16);           // 0 or 16 bytes (k half)
    const int b_r  = ((lane >> 4) << 3) + (lane & 7);   // row within n16 tile
    const int b_kb = ((lane >> 3) & 1) << 4;            // 0/16 bytes

    for (int c = 0; c < NC; c++) {
        const int s = c & 1;
        if (c + 1 < NC) CP_WAIT1(); else CP_WAIT0();
        __syncthreads();

        const uint32_t sa = sbase + s * 32768;
        const uint32_t sb = sa + 16384;

#pragma unroll
        for (int ks = 0; ks < 4; ks++) {
            uint32_t ar[2][4], br[4][4];
#pragma unroll
            for (int mi = 0; mi < 2; mi++) {
                int row = wm + mi * 16 + a_r;
                uint32_t kb = (uint32_t)(ks * 32 + a_kb) ^ ((row & 7) << 4);
                LDMATRIX_X4(ar[mi][0], ar[mi][1], ar[mi][2], ar[mi][3],
                            sa + row * 128 + kb);
            }
#pragma unroll
            for (int nj = 0; nj < 4; nj++) {
                int row = wn + nj * 16 + b_r;
                uint32_t kb = (uint32_t)(ks * 32 + b_kb) ^ ((row & 7) << 4);
                LDMATRIX_X4(br[nj][0], br[nj][1], br[nj][2], br[nj][3],
                            sb + row * 128 + kb);
            }
#pragma unroll
            for (int mi = 0; mi < 2; mi++)
#pragma unroll
                for (int nj = 0; nj < 4; nj++) {
                    MMA16816(acc[mi][nj * 2],     ar[mi], br[nj][0], br[nj][1]);
                    MMA16816(acc[mi][nj * 2 + 1], ar[mi], br[nj][2], br[nj][3]);
                }
        }
        __syncthreads();
        if (c + 2 < NC) load_chunk(c + 2, s);
    }

    // ---- epilogue ----
    const int er = lane >> 2;           // 0..7
    const int ec = (lane & 3) * 2;      // 0,2,4,6
#pragma unroll
    for (int mi = 0; mi < 2; mi++) {
#pragma unroll
        for (int half = 0; half < 2; half++) {
            const int R = mb + wm + mi * 16 + er + half * 8;
            float* Crow;
            if (EPI == 0) {
                Crow = C + (long)R * ldc;
            } else {
                const int b2 = R >> 10, j = R & 1023, mq = j >> 6, nq = j & 63;
                Crow = C + (long)(((nq << 4) + mq) * 8 + b2) * CC;
            }
#pragma unroll
            for (int nj = 0; nj < 8; nj++) {
                const int col = nb + wn + nj * 8 + ec;
                float v0 = acc[mi][nj][half * 2];
                float v1 = acc[mi][nj][half * 2 + 1];
                if (EPI == 1) { v0 += bias[col]; v1 += bias[col + 1]; }
                *(float2*)&Crow[col] = make_float2(v0, v1);
            }
        }
    }
}

// ---------------------------------------------------------------------------
// conv3: fp32 [R][512] -> bf16 [R][1536]. MODE 0 = A (hi|lo|hi), 1 = B (hi|hi|lo)
// ---------------------------------------------------------------------------
template<int MODE>
__global__ void conv3_kernel(const float* __restrict__ in, __nv_bfloat16* __restrict__ out)
{
    const long r = blockIdx.x;
    const int t = threadIdx.x;                       // 128 threads, 4 cols each
    float4 v = ((const float4*)(in + r * CC))[t];
    __nv_bfloat16 h0,h1,h2,h3,l0,l1,l2,l3;
    split_bf16(v.x,h0,l0); split_bf16(v.y,h1,l1);
    split_bf16(v.z,h2,l2); split_bf16(v.w,h3,l3);
    ushort4 hp = make_ushort4(bfr(h0),bfr(h1),bfr(h2),bfr(h3));
    ushort4 lp = make_ushort4(bfr(l0),bfr(l1),bfr(l2),bfr(l3));
    __nv_bfloat16* base = out + r * K3;
    ((ushort4*)(base))[t]          = hp;
    ((ushort4*)(base + CC))[t]     = MODE ? hp : lp;
    ((ushort4*)(base + 2*CC))[t]   = MODE ? lp : hp;
}

// ---------------------------------------------------------------------------
// norm: L2 row-normalize [R][512] fp32, emit split-bf16 trio rows.
// REORDER=1: q rows (n,m,b) -> row b*1024 + m*64 + n.
// ---------------------------------------------------------------------------
template<int REORDER, int MODE>
__global__ void norm_kernel(const float* __restrict__ in, __nv_bfloat16* __restrict__ out)
{
    const int r = blockIdx.x;
    const int t = threadIdx.x;                       // 128 threads
    float4 v = ((const float4*)(in + (long)r * CC))[t];
    float ss = v.x*v.x + v.y*v.y + v.z*v.z + v.w*v.w;
#pragma unroll
    for (int o = 16; o; o >>= 1) ss += __shfl_xor_sync(0xffffffffu, ss, o);
    __shared__ float sw[4];
    if ((t & 31) == 0) sw[t >> 5] = ss;
    __syncthreads();
    float tot = sw[0] + sw[1] + sw[2] + sw[3];
    float scale = 1.0f / fmaxf(sqrtf(tot), 1e-12f);

    long orow;
    if (REORDER) {
        int n = r >> 7, m = (r >> 3) & 15, b = r & 7;
        orow = (long)(b * 1024 + m * 64 + n);
    } else orow = r;

    __nv_bfloat16 h0,h1,h2,h3,l0,l1,l2,l3;
    split_bf16(v.x*scale,h0,l0); split_bf16(v.y*scale,h1,l1);
    split_bf16(v.z*scale,h2,l2); split_bf16(v.w*scale,h3,l3);
    ushort4 hp = make_ushort4(bfr(h0),bfr(h1),bfr(h2),bfr(h3));
    ushort4 lp = make_ushort4(bfr(l0),bfr(l1),bfr(l2),bfr(l3));
    __nv_bfloat16* base = out + orow * K3;
    ((ushort4*)(base))[t]        = hp;
    ((ushort4*)(base + CC))[t]   = MODE ? hp : lp;
    ((ushort4*)(base + 2*CC))[t] = MODE ? lp : hp;
}

// ---------------------------------------------------------------------------
// Transpose + split-convert: in fp32 [b][256][W] -> out bf16 [b][W][768]
// ---------------------------------------------------------------------------
template<int MODE>
__global__ void trconv_kernel(const float* __restrict__ in, __nv_bfloat16* __restrict__ out, int W)
{
    __shared__ float s[32][33];
    const int b = blockIdx.z;
    const float* ib = in + (long)b * 256 * W;
    __nv_bfloat16* ob = out + (long)b * W * 768;
    const int k0 = blockIdx.y * 32, w0 = blockIdx.x * 32;
    const int tx = threadIdx.x, ty = threadIdx.y;    // (32, 8)
#pragma unroll
    for (int i = 0; i < 4; i++)
        s[ty + 8*i][tx] = ib[(long)(k0 + ty + 8*i) * W + w0 + tx];
    __syncthreads();
#pragma unroll
    for (int i = 0; i < 4; i++) {
        const int wrow = w0 + ty + 8*i;
        float x = s[tx][ty + 8*i];
        __nv_bfloat16 h, l; split_bf16(x, h, l);
        __nv_bfloat16* p = ob + (long)wrow * 768 + k0 + tx;
        p[0]   = h;
        p[256] = MODE ? h : l;
        p[512] = MODE ? l : h;
    }
}

// ---------------------------------------------------------------------------
// Sinkhorn (validated R1): one warp per (b,k) problem, scaling-domain.
// ---------------------------------------------------------------------------
__global__ __launch_bounds__(256)
void sinkhorn_kernel(const float* __restrict__ sim, float* __restrict__ T,
                     float* __restrict__ score)
{
    const int p    = blockIdx.x * 8 + (threadIdx.x >> 5);
    const int lane = threadIdx.x & 31;
    const float* srow = sim + (long)p * (MMQ * NQ);

    float Km[32];
#pragma unroll
    for (int i = 0; i < 16; i++) {
        Km[i]      = __expf((srow[i * 64 + lane]      - 1.0f) * INV_EPS);
        Km[i + 16] = __expf((srow[i * 64 + lane + 32] - 1.0f) * INV_EPS);
    }

    const float MU = 1.0f / 16.0f + 1e-8f;
    const float NU = 1.0f / 64.0f + 1e-8f;
    float b0 = 1.0f, b1 = 1.0f;
    float a[16];

#pragma unroll 1
    for (int iter = 0; iter < 100; iter++) {
        float v[16];
#pragma unroll
        for (int i = 0; i < 16; i++) v[i] = Km[i] * b0 + Km[i + 16] * b1;
#pragma unroll
        for (int i = 0; i < 16; i++) v[i] += __shfl_xor_sync(0xffffffffu, v[i], 16);
#pragma unroll
        for (int i = 0; i < 8; i++) {
            float t0 = v[i], t1 = v[i + 8];
            float r0 = __shfl_xor_sync(0xffffffffu, t0, 8);
            float r1 = __shfl_xor_sync(0xffffffffu, t1, 8);
            v[i] = (lane & 8) ? (t1 + r1) : (t0 + r0);
        }
#pragma unroll
        for (int i = 0; i < 4; i++) {
            float t0 = v[i], t1 = v[i + 4];
            float r0 = __shfl_xor_sync(0xffffffffu, t0, 4);
            float r1 = __shfl_xor_sync(0xffffffffu, t1, 4);
            v[i] = (lane & 4) ? (t1 + r1) : (t0 + r0);
        }
#pragma unroll
        for (int i = 0; i < 2; i++) {
            float t0 = v[i], t1 = v[i + 2];
            float r0 = __shfl_xor_sync(0xffffffffu, t0, 2);
            float r1 = __shfl_xor_sync(0xffffffffu, t1, 2);
            v[i] = (lane & 2) ? (t1 + r1) : (t0 + r0);
        }
        {
            float t0 = v[0], t1 = v[1];
            float r0 = __shfl_xor_sync(0xffffffffu, t0, 1);
            float r1 = __shfl_xor_sync(0xffffffffu, t1, 1);
            v[0] = (lane & 1) ? (t1 + r1) : (t0 + r0);
        }
        float av = __fdividef(MU, v[0]);
#pragma unroll
        for (int i = 0; i < 16; i++) a[i] = __shfl_sync(0xffffffffu, av, i);

        float c0a = 0.f, c0b = 0.f, c1a = 0.f, c1b = 0.f;
#pragma unroll
        for (int i = 0; i < 16; i += 2) {
            c0a += Km[i] * a[i];       c0b += Km[i + 1] * a[i + 1];
            c1a += Km[i + 16] * a[i];  c1b += Km[i + 17] * a[i + 1];
        }
        b0 = __fdividef(NU, c0a + c0b);
        b1 = __fdividef(NU, c1a + c1b);
    }

    float* Trow = T + (long)p * (MMQ * NQ);
    float* Srow = score + (long)p * (MMQ * NQ);
#pragma unroll
    for (int i = 0; i < 16; i++) {
        float T0 = a[i] * Km[i] * b0;
        float T1 = a[i] * Km[i + 16] * b1;
        Trow[i * 64 + lane]      = T0;
        Trow[i * 64 + lane + 32] = T1;
        Srow[i * 64 + lane]      = 1024.0f * srow[i * 64 + lane] * T0;
        Srow[i * 64 + lane + 32] = 1024.0f * srow[i * 64 + lane + 32] * T1;
    }
}

// ---------------------------------------------------------------------------
extern "C" void kernel_launch(void* const* d_in, const int* in_sizes, int n_in,
                              void* d_out, int out_size)
{
    const float* xq = (const float*)d_in[0];
    const float* xk = (const float*)d_in[1];
    const float* xv = (const float*)d_in[2];
    const float* Wq = (const float*)d_in[3];
    const float* Wk = (const float*)d_in[4];
    const float* Wv = (const float*)d_in[5];
    const float* Wp = (const float*)d_in[6];
    const float* bp = (const float*)d_in[7];
    float* out_x     = (float*)d_out;
    float* out_score = out_x + X_ELEMS;

    __nv_bfloat16 *xq3,*xk3,*xv3,*wq3,*wk3,*wv3,*wp3,*qr3,*kn3,*Tt3,*vT3,*y3;
    float *qlin,*klin,*vbuf,*sim,*T,*y;
    cudaGetSymbolAddress((void**)&xq3, g_xq3);
    cudaGetSymbolAddress((void**)&xk3, g_xk3);
    cudaGetSymbolAddress((void**)&xv3, g_xv3);
    cudaGetSymbolAddress((void**)&wq3, g_wq3);
    cudaGetSymbolAddress((void**)&wk3, g_wk3);
    cudaGetSymbolAddress((void**)&wv3, g_wv3);
    cudaGetSymbolAddress((void**)&wp3, g_wp3);
    cudaGetSymbolAddress((void**)&qr3, g_qr3);
    cudaGetSymbolAddress((void**)&kn3, g_kn3);
    cudaGetSymbolAddress((void**)&Tt3, g_Tt3);
    cudaGetSymbolAddress((void**)&vT3, g_vT3);
    cudaGetSymbolAddress((void**)&y3,  g_y3);
    cudaGetSymbolAddress((void**)&qlin, g_qlin);
    cudaGetSymbolAddress((void**)&klin, g_klin);
    cudaGetSymbolAddress((void**)&vbuf, g_v);
    cudaGetSymbolAddress((void**)&sim,  g_sim);
    cudaGetSymbolAddress((void**)&T,    g_T);
    cudaGetSymbolAddress((void**)&y,    g_y);

    cudaFuncSetAttribute(hgemm<0>, cudaFuncAttributeMaxDynamicSharedMemorySize, GSMEM);
    cudaFuncSetAttribute(hgemm<1>, cudaFuncAttributeMaxDynamicSharedMemorySize, GSMEM);

    // --- split-bf16 conversions (weights: B-mode, activations: A-mode) ---
    conv3_kernel<1><<<CC, 128>>>(Wq, wq3);
    conv3_kernel<1><<<CC, 128>>>(Wk, wk3);
    conv3_kernel<1><<<CC, 128>>>(Wv, wv3);
    conv3_kernel<1><<<CC, 128>>>(Wp, wp3);
    conv3_kernel<0><<<NROWS_Q, 128>>>(xq, xq3);
    conv3_kernel<0><<<NROWS_K, 128>>>(xk, xk3);
    conv3_kernel<0><<<NROWS_K, 128>>>(xv, xv3);

    // --- projections (tensor cores, split-bf16) ---
    hgemm<0><<<dim3(4, 64, 1), 256, GSMEM>>>(xq3, wq3, qlin, nullptr, K3, CC, 0, 0, 0);
    hgemm<0><<<dim3(4, 16, 1), 256, GSMEM>>>(xk3, wk3, klin, nullptr, K3, CC, 0, 0, 0);
    hgemm<0><<<dim3(4, 16, 1), 256, GSMEM>>>(xv3, wv3, vbuf, nullptr, K3, CC, 0, 0, 0);

    // --- l2 normalize; q reordered to [b][m*64+n], both emitted as split-bf16 ---
    norm_kernel<1, 1><<<NROWS_Q, 128>>>(qlin, qr3);   // q: B-operand of sim
    norm_kernel<0, 0><<<NROWS_K, 128>>>(klin, kn3);   // k: A-operand of sim

    // --- sim[b][k][m*64+n] (fp32) ---
    hgemm<0><<<dim3(8, 2, 8), 256, GSMEM>>>(
        kn3, qr3, sim, nullptr, K3, 1024,
        (long)256 * K3, (long)1024 * K3, (long)256 * 1024);

    // --- Sinkhorn -> T + score_map ---
    sinkhorn_kernel<<<BKP / 8, 256>>>(sim, T, out_score);

    // --- transpose+convert T and v for attn·v GEMM ---
    trconv_kernel<0><<<dim3(32, 8, 8), dim3(32, 8)>>>(T, Tt3, 1024);
    trconv_kernel<1><<<dim3(16, 8, 8), dim3(32, 8)>>>(vbuf, vT3, 512);

    // --- y[b][m*64+n][c] = T^T · v ---
    hgemm<0><<<dim3(4, 8, 8), 256, GSMEM>>>(
        Tt3, vT3, y, nullptr, 768, CC,
        (long)1024 * 768, (long)512 * 768, (long)1024 * CC);

    // --- out projection + bias + scatter to (n,m,b,c) ---
    conv3_kernel<0><<<NROWS_Q, 128>>>(y, y3);
    hgemm<1><<<dim3(4, 64, 1), 256, GSMEM>>>(y3, wp3, out_x, bp, K3, CC, 0, 0, 0);
}

// round 4
// speedup vs baseline: 2.1067x; 1.1912x over previous
#include <cuda_runtime.h>
#include <cuda_bf16.h>
#include <cstdint>
#include <math.h>

// ---------------------------------------------------------------------------
// Problem constants
// ---------------------------------------------------------------------------
#define NQ   64
#define MMQ  16
#define BB   8
#define KK   256
#define CC   512
#define K3   1536           // 3*CC for split-bf16 GEMMs
#define NROWS_Q 8192
#define NROWS_K 2048
#define BKP     2048
#define INV_EPS 20.0f
#define X_ELEMS (NROWS_Q*CC)

// ---------------------------------------------------------------------------
// Scratch (device globals; no allocation allowed)
// ---------------------------------------------------------------------------
__device__ __nv_bfloat16 g_xq3[NROWS_Q*K3];
__device__ __nv_bfloat16 g_xk3[NROWS_K*K3];
__device__ __nv_bfloat16 g_xv3[NROWS_K*K3];
__device__ __nv_bfloat16 g_wq3[CC*K3];
__device__ __nv_bfloat16 g_wk3[CC*K3];
__device__ __nv_bfloat16 g_wv3[CC*K3];
__device__ __nv_bfloat16 g_wp3[CC*K3];
__device__ float g_qlin[NROWS_Q*CC];
__device__ float g_klin[NROWS_K*CC];
__device__ float g_v   [NROWS_K*CC];
__device__ __nv_bfloat16 g_qr3[NROWS_Q*K3];
__device__ __nv_bfloat16 g_kn3[NROWS_K*K3];
__device__ float g_sim[BKP*MMQ*NQ];
__device__ float g_T  [BKP*MMQ*NQ];
__device__ __nv_bfloat16 g_Tt3[BB*1024*768];
__device__ __nv_bfloat16 g_vT3[BB*512*768];
__device__ __nv_bfloat16 g_y3[NROWS_Q*K3];

// ---------------------------------------------------------------------------
// PTX helpers
// ---------------------------------------------------------------------------
__device__ __forceinline__ uint32_t s2u(const void* p){
    uint32_t a;
    asm("{ .reg .u64 t; cvta.to.shared.u64 t, %1; cvt.u32.u64 %0, t; }"
        : "=r"(a) : "l"(p));
    return a;
}

#define CP_ASYNC16(dst, src) \
    asm volatile("cp.async.cg.shared.global [%0], [%1], 16;" :: "r"(dst), "l"(src) : "memory")
#define CP_COMMIT() asm volatile("cp.async.commit_group;" ::: "memory")
#define CP_WAIT1()  asm volatile("cp.async.wait_group 1;" ::: "memory")
#define CP_WAIT0()  asm volatile("cp.async.wait_group 0;" ::: "memory")

#define LDMATRIX_X4(r0, r1, r2, r3, addr) \
    asm volatile("ldmatrix.sync.aligned.m8n8.x4.shared.b16 {%0,%1,%2,%3}, [%4];" \
                 : "=r"(r0), "=r"(r1), "=r"(r2), "=r"(r3) : "r"(addr))

#define MMA16816(d, a, b0, b1) \
    asm volatile("mma.sync.aligned.m16n8k16.row.col.f32.bf16.bf16.f32 " \
                 "{%0,%1,%2,%3}, {%4,%5,%6,%7}, {%8,%9}, {%0,%1,%2,%3};" \
                 : "+f"((d)[0]), "+f"((d)[1]), "+f"((d)[2]), "+f"((d)[3]) \
                 : "r"((a)[0]), "r"((a)[1]), "r"((a)[2]), "r"((a)[3]), \
                   "r"(b0), "r"(b1))

__device__ __forceinline__ unsigned short bfr(__nv_bfloat16 h){
    return *reinterpret_cast<unsigned short*>(&h);
}
__device__ __forceinline__ void split_bf16(float x, __nv_bfloat16& h, __nv_bfloat16& l){
    h = __float2bfloat16(x);
    l = __float2bfloat16(x - __bfloat162float(h));
}
__device__ __forceinline__ uint32_t pack2(__nv_bfloat16 a, __nv_bfloat16 b){
    return (uint32_t)bfr(a) | ((uint32_t)bfr(b) << 16);
}

// ---------------------------------------------------------------------------
// HMMA GEMM core: C[M,N] = A(M,K')·B(N,K')ᵀ, K-major bf16, fp32 accum.
// CTA tile 128x128, BK=64, 3-stage cp.async ring (single barrier per chunk),
// 8 warps (4m x 2n), warp tile 32x64 via mma.sync.m16n8k16.
// EPI=0 plain fp32 store; EPI=1 out-proj scatter+bias; EPI=2 split-bf16 emit.
// ---------------------------------------------------------------------------
#define STG   32768
#define GSMEM (3*STG)

template<int EPI>
__device__ __forceinline__
void gemm_core(const __nv_bfloat16* __restrict__ A, const __nv_bfloat16* __restrict__ B,
               void* __restrict__ Cv, const float* __restrict__ bias,
               int Kp, int ldc, int mb, int nb, int bz, long cStride,
               char* smem)
{
    const int tid  = threadIdx.x;
    const int w    = tid >> 5;
    const int lane = tid & 31;
    const int wm   = (w & 3) * 32;
    const int wn   = (w >> 2) * 64;

    const uint32_t sbase = s2u(smem);
    const int NC = Kp >> 6;

    const int lrow = tid >> 1;
    const int lcg0 = (tid & 1) * 4;

    auto load_chunk = [&](int c, int s){
        const uint32_t st = sbase + s * STG;
        const __nv_bfloat16* Ag = A + (long)(mb + lrow) * Kp + c * 64 + lcg0 * 8;
        const __nv_bfloat16* Bg = B + (long)(nb + lrow) * Kp + c * 64 + lcg0 * 8;
        const uint32_t rbase = lrow * 128;
        const uint32_t sw    = (lrow & 7) << 4;
#pragma unroll
        for (int j = 0; j < 4; j++) {
            uint32_t off = rbase + (((lcg0 + j) << 4) ^ sw);
            CP_ASYNC16(st + off, Ag + j * 8);
            CP_ASYNC16(st + 16384 + off, Bg + j * 8);
        }
        CP_COMMIT();
    };

    float acc[2][8][4];
#pragma unroll
    for (int i = 0; i < 2; i++)
#pragma unroll
        for (int j = 0; j < 8; j++)
#pragma unroll
            for (int q = 0; q < 4; q++) acc[i][j][q] = 0.f;

    load_chunk(0, 0);
    load_chunk(1, 1);

    const int a_r  = lane & 15;
    const int a_kb = (lane & 16);
    const int b_r  = ((lane >> 4) << 3) + (lane & 7);
    const int b_kb = ((lane >> 3) & 1) << 4;

    int stage = 0;
    for (int c = 0; c < NC; c++) {
        if (c + 1 < NC) CP_WAIT1(); else CP_WAIT0();
        __syncthreads();

        // issue next loads FIRST (into the stage freed at iteration c-1)
        if (c + 2 < NC) {
            int ns = stage + 2; if (ns >= 3) ns -= 3;
            load_chunk(c + 2, ns);
        }

        const uint32_t sa = sbase + stage * STG;
        const uint32_t sb = sa + 16384;

#pragma unroll
        for (int ks = 0; ks < 4; ks++) {
            uint32_t ar[2][4], br[4][4];
#pragma unroll
            for (int mi = 0; mi < 2; mi++) {
                int row = wm + mi * 16 + a_r;
                uint32_t kb = (uint32_t)(ks * 32 + a_kb) ^ ((row & 7) << 4);
                LDMATRIX_X4(ar[mi][0], ar[mi][1], ar[mi][2], ar[mi][3],
                            sa + row * 128 + kb);
            }
#pragma unroll
            for (int nj = 0; nj < 4; nj++) {
                int row = wn + nj * 16 + b_r;
                uint32_t kb = (uint32_t)(ks * 32 + b_kb) ^ ((row & 7) << 4);
                LDMATRIX_X4(br[nj][0], br[nj][1], br[nj][2], br[nj][3],
                            sb + row * 128 + kb);
            }
#pragma unroll
            for (int mi = 0; mi < 2; mi++)
#pragma unroll
                for (int nj = 0; nj < 4; nj++) {
                    MMA16816(acc[mi][nj * 2],     ar[mi], br[nj][0], br[nj][1]);
                    MMA16816(acc[mi][nj * 2 + 1], ar[mi], br[nj][2], br[nj][3]);
                }
        }
        stage++; if (stage == 3) stage = 0;
    }

    // ---- epilogue ----
    const int er = lane >> 2;
    const int ec = (lane & 3) * 2;
#pragma unroll
    for (int mi = 0; mi < 2; mi++) {
#pragma unroll
        for (int half = 0; half < 2; half++) {
            const int R = mb + wm + mi * 16 + er + half * 8;
            if (EPI == 0) {
                float* Crow = (float*)Cv + bz * cStride + (long)R * ldc;
#pragma unroll
                for (int nj = 0; nj < 8; nj++) {
                    const int col = nb + wn + nj * 8 + ec;
                    *(float2*)&Crow[col] =
                        make_float2(acc[mi][nj][half * 2], acc[mi][nj][half * 2 + 1]);
                }
            } else if (EPI == 1) {
                const int b2 = R >> 10, j = R & 1023, mq = j >> 6, nq = j & 63;
                float* Crow = (float*)Cv + (long)(((nq << 4) + mq) * 8 + b2) * CC;
#pragma unroll
                for (int nj = 0; nj < 8; nj++) {
                    const int col = nb + wn + nj * 8 + ec;
                    *(float2*)&Crow[col] = make_float2(
                        acc[mi][nj][half * 2] + bias[col],
                        acc[mi][nj][half * 2 + 1] + bias[col + 1]);
                }
            } else {
                // split-bf16 A-mode emit: row R of batch bz -> y3[bz*1024+R][hi|lo|hi]
                __nv_bfloat16* Yr = (__nv_bfloat16*)Cv + bz * cStride + (long)R * K3;
#pragma unroll
                for (int nj = 0; nj < 8; nj++) {
                    const int col = nb + wn + nj * 8 + ec;
                    __nv_bfloat16 h0, l0, h1, l1;
                    split_bf16(acc[mi][nj][half * 2],     h0, l0);
                    split_bf16(acc[mi][nj][half * 2 + 1], h1, l1);
                    uint32_t hp = pack2(h0, h1), lp = pack2(l0, l1);
                    *(uint32_t*)&Yr[col]        = hp;
                    *(uint32_t*)&Yr[col + CC]   = lp;
                    *(uint32_t*)&Yr[col + 2*CC] = hp;
                }
            }
        }
    }
}

// Generic single-source GEMM
template<int EPI>
__global__ __launch_bounds__(256, 2)
void hgemm(const __nv_bfloat16* __restrict__ A, const __nv_bfloat16* __restrict__ B,
           void* __restrict__ C, const float* __restrict__ bias,
           int Kp, int ldc, long aStride, long bStride, long cStride)
{
    extern __shared__ char smem[];
    const int bz = blockIdx.z;
    gemm_core<EPI>(A + bz * aStride, B + bz * bStride, C, bias,
                   Kp, ldc, blockIdx.y * 128, blockIdx.x * 128, bz, cStride, smem);
}

// Fused q/k/v projection: grid.y in [0,96): 0-63 q, 64-79 k, 80-95 v
__global__ __launch_bounds__(256, 2)
void hgemm_proj(const __nv_bfloat16* __restrict__ Aq, const __nv_bfloat16* __restrict__ Bq,
                float* __restrict__ Cq,
                const __nv_bfloat16* __restrict__ Ak, const __nv_bfloat16* __restrict__ Bk,
                float* __restrict__ Ck,
                const __nv_bfloat16* __restrict__ Av, const __nv_bfloat16* __restrict__ Bv,
                float* __restrict__ Cv)
{
    extern __shared__ char smem[];
    const int by = blockIdx.y;
    const __nv_bfloat16 *A, *B;
    float* C;
    int mb;
    if (by < 64)      { A = Aq; B = Bq; C = Cq; mb = by * 128; }
    else if (by < 80) { A = Ak; B = Bk; C = Ck; mb = (by - 64) * 128; }
    else              { A = Av; B = Bv; C = Cv; mb = (by - 80) * 128; }
    gemm_core<0>(A, B, C, nullptr, K3, CC, mb, blockIdx.x * 128, 0, 0, smem);
}

// ---------------------------------------------------------------------------
// conv3 merged: fp32 [512] rows -> bf16 trio rows. Weights (MODE B) x4 tensors.
// ---------------------------------------------------------------------------
__device__ __forceinline__ void conv3_row(const float* __restrict__ in,
                                          __nv_bfloat16* __restrict__ out,
                                          int t, int mode)
{
    float4 v = ((const float4*)in)[t];
    __nv_bfloat16 h0,h1,h2,h3,l0,l1,l2,l3;
    split_bf16(v.x,h0,l0); split_bf16(v.y,h1,l1);
    split_bf16(v.z,h2,l2); split_bf16(v.w,h3,l3);
    ushort4 hp = make_ushort4(bfr(h0),bfr(h1),bfr(h2),bfr(h3));
    ushort4 lp = make_ushort4(bfr(l0),bfr(l1),bfr(l2),bfr(l3));
    ((ushort4*)(out))[t]        = hp;
    ((ushort4*)(out + CC))[t]   = mode ? hp : lp;
    ((ushort4*)(out + 2*CC))[t] = mode ? lp : hp;
}

__global__ void conv3_weights(const float* __restrict__ w0, __nv_bfloat16* __restrict__ o0,
                              const float* __restrict__ w1, __nv_bfloat16* __restrict__ o1,
                              const float* __restrict__ w2, __nv_bfloat16* __restrict__ o2,
                              const float* __restrict__ w3, __nv_bfloat16* __restrict__ o3)
{
    const int r = blockIdx.x;
    const int sel = r >> 9, rw = r & 511;
    const float* in; __nv_bfloat16* out;
    if (sel == 0)      { in = w0; out = o0; }
    else if (sel == 1) { in = w1; out = o1; }
    else if (sel == 2) { in = w2; out = o2; }
    else               { in = w3; out = o3; }
    conv3_row(in + (long)rw * CC, out + (long)rw * K3, threadIdx.x, 1);
}

__global__ void conv3_acts(const float* __restrict__ xq, __nv_bfloat16* __restrict__ oq,
                           const float* __restrict__ xk, __nv_bfloat16* __restrict__ ok,
                           const float* __restrict__ xv, __nv_bfloat16* __restrict__ ov)
{
    const int r = blockIdx.x;       // 0..12287
    const float* in; __nv_bfloat16* out; int rr;
    if (r < 8192)       { in = xq; out = oq; rr = r; }
    else if (r < 10240) { in = xk; out = ok; rr = r - 8192; }
    else                { in = xv; out = ov; rr = r - 10240; }
    conv3_row(in + (long)rr * CC, out + (long)rr * K3, threadIdx.x, 0);
}

// ---------------------------------------------------------------------------
// norm: L2 row-normalize [R][512] fp32, emit split-bf16 trio rows.
// REORDER=1: q rows (n,m,b) -> row b*1024 + m*64 + n.
// ---------------------------------------------------------------------------
template<int REORDER, int MODE>
__global__ void norm_kernel(const float* __restrict__ in, __nv_bfloat16* __restrict__ out)
{
    const int r = blockIdx.x;
    const int t = threadIdx.x;
    float4 v = ((const float4*)(in + (long)r * CC))[t];
    float ss = v.x*v.x + v.y*v.y + v.z*v.z + v.w*v.w;
#pragma unroll
    for (int o = 16; o; o >>= 1) ss += __shfl_xor_sync(0xffffffffu, ss, o);
    __shared__ float sw[4];
    if ((t & 31) == 0) sw[t >> 5] = ss;
    __syncthreads();
    float tot = sw[0] + sw[1] + sw[2] + sw[3];
    float scale = 1.0f / fmaxf(sqrtf(tot), 1e-12f);

    long orow;
    if (REORDER) {
        int n = r >> 7, m = (r >> 3) & 15, b = r & 7;
        orow = (long)(b * 1024 + m * 64 + n);
    } else orow = r;

    __nv_bfloat16 h0,h1,h2,h3,l0,l1,l2,l3;
    split_bf16(v.x*scale,h0,l0); split_bf16(v.y*scale,h1,l1);
    split_bf16(v.z*scale,h2,l2); split_bf16(v.w*scale,h3,l3);
    ushort4 hp = make_ushort4(bfr(h0),bfr(h1),bfr(h2),bfr(h3));
    ushort4 lp = make_ushort4(bfr(l0),bfr(l1),bfr(l2),bfr(l3));
    __nv_bfloat16* base = out + orow * K3;
    ((ushort4*)(base))[t]        = hp;
    ((ushort4*)(base + CC))[t]   = MODE ? hp : lp;
    ((ushort4*)(base + 2*CC))[t] = MODE ? lp : hp;
}

// ---------------------------------------------------------------------------
// Transpose + split-convert: in fp32 [b][256][W] -> out bf16 [b][W][768]
// ---------------------------------------------------------------------------
template<int MODE>
__global__ void trconv_kernel(const float* __restrict__ in, __nv_bfloat16* __restrict__ out, int W)
{
    __shared__ float s[32][33];
    const int b = blockIdx.z;
    const float* ib = in + (long)b * 256 * W;
    __nv_bfloat16* ob = out + (long)b * W * 768;
    const int k0 = blockIdx.y * 32, w0 = blockIdx.x * 32;
    const int tx = threadIdx.x, ty = threadIdx.y;
#pragma unroll
    for (int i = 0; i < 4; i++)
        s[ty + 8*i][tx] = ib[(long)(k0 + ty + 8*i) * W + w0 + tx];
    __syncthreads();
#pragma unroll
    for (int i = 0; i < 4; i++) {
        const int wrow = w0 + ty + 8*i;
        float x = s[tx][ty + 8*i];
        __nv_bfloat16 h, l; split_bf16(x, h, l);
        __nv_bfloat16* p = ob + (long)wrow * 768 + k0 + tx;
        p[0]   = h;
        p[256] = MODE ? h : l;
        p[512] = MODE ? l : h;
    }
}

// ---------------------------------------------------------------------------
// Sinkhorn (validated): one warp per (b,k) problem, scaling-domain.
// ---------------------------------------------------------------------------
__global__ __launch_bounds__(256)
void sinkhorn_kernel(const float* __restrict__ sim, float* __restrict__ T,
                     float* __restrict__ score)
{
    const int p    = blockIdx.x * 8 + (threadIdx.x >> 5);
    const int lane = threadIdx.x & 31;
    const float* srow = sim + (long)p * (MMQ * NQ);

    float Km[32];
#pragma unroll
    for (int i = 0; i < 16; i++) {
        Km[i]      = __expf((srow[i * 64 + lane]      - 1.0f) * INV_EPS);
        Km[i + 16] = __expf((srow[i * 64 + lane + 32] - 1.0f) * INV_EPS);
    }

    const float MU = 1.0f / 16.0f + 1e-8f;
    const float NU = 1.0f / 64.0f + 1e-8f;
    float b0 = 1.0f, b1 = 1.0f;
    float a[16];

#pragma unroll 1
    for (int iter = 0; iter < 100; iter++) {
        float v[16];
#pragma unroll
        for (int i = 0; i < 16; i++) v[i] = Km[i] * b0 + Km[i + 16] * b1;
#pragma unroll
        for (int i = 0; i < 16; i++) v[i] += __shfl_xor_sync(0xffffffffu, v[i], 16);
#pragma unroll
        for (int i = 0; i < 8; i++) {
            float t0 = v[i], t1 = v[i + 8];
            float r0 = __shfl_xor_sync(0xffffffffu, t0, 8);
            float r1 = __shfl_xor_sync(0xffffffffu, t1, 8);
            v[i] = (lane & 8) ? (t1 + r1) : (t0 + r0);
        }
#pragma unroll
        for (int i = 0; i < 4; i++) {
            float t0 = v[i], t1 = v[i + 4];
            float r0 = __shfl_xor_sync(0xffffffffu, t0, 4);
            float r1 = __shfl_xor_sync(0xffffffffu, t1, 4);
            v[i] = (lane & 4) ? (t1 + r1) : (t0 + r0);
        }
#pragma unroll
        for (int i = 0; i < 2; i++) {
            float t0 = v[i], t1 = v[i + 2];
            float r0 = __shfl_xor_sync(0xffffffffu, t0, 2);
            float r1 = __shfl_xor_sync(0xffffffffu, t1, 2);
            v[i] = (lane & 2) ? (t1 + r1) : (t0 + r0);
        }
        {
            float t0 = v[0], t1 = v[1];
            float r0 = __shfl_xor_sync(0xffffffffu, t0, 1);
            float r1 = __shfl_xor_sync(0xffffffffu, t1, 1);
            v[0] = (lane & 1) ? (t1 + r1) : (t0 + r0);
        }
        float av = __fdividef(MU, v[0]);
#pragma unroll
        for (int i = 0; i < 16; i++) a[i] = __shfl_sync(0xffffffffu, av, i);

        float c0a = 0.f, c0b = 0.f, c1a = 0.f, c1b = 0.f;
#pragma unroll
        for (int i = 0; i < 16; i += 2) {
            c0a += Km[i] * a[i];       c0b += Km[i + 1] * a[i + 1];
            c1a += Km[i + 16] * a[i];  c1b += Km[i + 17] * a[i + 1];
        }
        b0 = __fdividef(NU, c0a + c0b);
        b1 = __fdividef(NU, c1a + c1b);
    }

    float* Trow = T + (long)p * (MMQ * NQ);
    float* Srow = score + (long)p * (MMQ * NQ);
#pragma unroll
    for (int i = 0; i < 16; i++) {
        float T0 = a[i] * Km[i] * b0;
        float T1 = a[i] * Km[i + 16] * b1;
        Trow[i * 64 + lane]      = T0;
        Trow[i * 64 + lane + 32] = T1;
        Srow[i * 64 + lane]      = 1024.0f * srow[i * 64 + lane] * T0;
        Srow[i * 64 + lane + 32] = 1024.0f * srow[i * 64 + lane + 32] * T1;
    }
}

// ---------------------------------------------------------------------------
extern "C" void kernel_launch(void* const* d_in, const int* in_sizes, int n_in,
                              void* d_out, int out_size)
{
    const float* xq = (const float*)d_in[0];
    const float* xk = (const float*)d_in[1];
    const float* xv = (const float*)d_in[2];
    const float* Wq = (const float*)d_in[3];
    const float* Wk = (const float*)d_in[4];
    const float* Wv = (const float*)d_in[5];
    const float* Wp = (const float*)d_in[6];
    const float* bp = (const float*)d_in[7];
    float* out_x     = (float*)d_out;
    float* out_score = out_x + X_ELEMS;

    __nv_bfloat16 *xq3,*xk3,*xv3,*wq3,*wk3,*wv3,*wp3,*qr3,*kn3,*Tt3,*vT3,*y3;
    float *qlin,*klin,*vbuf,*sim,*T;
    cudaGetSymbolAddress((void**)&xq3, g_xq3);
    cudaGetSymbolAddress((void**)&xk3, g_xk3);
    cudaGetSymbolAddress((void**)&xv3, g_xv3);
    cudaGetSymbolAddress((void**)&wq3, g_wq3);
    cudaGetSymbolAddress((void**)&wk3, g_wk3);
    cudaGetSymbolAddress((void**)&wv3, g_wv3);
    cudaGetSymbolAddress((void**)&wp3, g_wp3);
    cudaGetSymbolAddress((void**)&qr3, g_qr3);
    cudaGetSymbolAddress((void**)&kn3, g_kn3);
    cudaGetSymbolAddress((void**)&Tt3, g_Tt3);
    cudaGetSymbolAddress((void**)&vT3, g_vT3);
    cudaGetSymbolAddress((void**)&y3,  g_y3);
    cudaGetSymbolAddress((void**)&qlin, g_qlin);
    cudaGetSymbolAddress((void**)&klin, g_klin);
    cudaGetSymbolAddress((void**)&vbuf, g_v);
    cudaGetSymbolAddress((void**)&sim,  g_sim);
    cudaGetSymbolAddress((void**)&T,    g_T);

    cudaFuncSetAttribute(hgemm<0>,   cudaFuncAttributeMaxDynamicSharedMemorySize, GSMEM);
    cudaFuncSetAttribute(hgemm<1>,   cudaFuncAttributeMaxDynamicSharedMemorySize, GSMEM);
    cudaFuncSetAttribute(hgemm<2>,   cudaFuncAttributeMaxDynamicSharedMemorySize, GSMEM);
    cudaFuncSetAttribute(hgemm_proj, cudaFuncAttributeMaxDynamicSharedMemorySize, GSMEM);

    // --- split-bf16 conversions (2 fused launches) ---
    conv3_weights<<<4 * CC, 128>>>(Wq, wq3, Wk, wk3, Wv, wv3, Wp, wp3);
    conv3_acts<<<12288, 128>>>(xq, xq3, xk, xk3, xv, xv3);

    // --- q/k/v projections: single fused launch (384 CTAs) ---
    hgemm_proj<<<dim3(4, 96, 1), 256, GSMEM>>>(
        xq3, wq3, qlin, xk3, wk3, klin, xv3, wv3, vbuf);

    // --- l2 normalize; q reordered to [b][m*64+n], split-bf16 emit ---
    norm_kernel<1, 1><<<NROWS_Q, 128>>>(qlin, qr3);   // q: B-operand of sim
    norm_kernel<0, 0><<<NROWS_K, 128>>>(klin, kn3);   // k: A-operand of sim

    // --- sim[b][k][m*64+n] (fp32) ---
    hgemm<0><<<dim3(8, 2, 8), 256, GSMEM>>>(
        kn3, qr3, sim, nullptr, K3, 1024,
        (long)256 * K3, (long)1024 * K3, (long)256 * 1024);

    // --- Sinkhorn -> T + score_map ---
    sinkhorn_kernel<<<BKP / 8, 256>>>(sim, T, out_score);

    // --- transpose+convert T and v for attn·v GEMM ---
    trconv_kernel<0><<<dim3(32, 8, 8), dim3(32, 8)>>>(T, Tt3, 1024);
    trconv_kernel<1><<<dim3(16, 8, 8), dim3(32, 8)>>>(vbuf, vT3, 512);

    // --- y3[b*1024+r][hi|lo|hi] = split(T^T · v): fused epilogue ---
    hgemm<2><<<dim3(4, 8, 8), 256, GSMEM>>>(
        Tt3, vT3, y3, nullptr, 768, 0,
        (long)1024 * 768, (long)512 * 768, (long)1024 * K3);

    // --- out projection + bias + scatter to (n,m,b,c) ---
    hgemm<1><<<dim3(4, 64, 1), 256, GSMEM>>>(
        y3, wp3, out_x, bp, K3, CC, 0, 0, 0);
}

// round 5
// speedup vs baseline: 2.1252x; 1.0088x over previous
#include <cuda_runtime.h>
#include <cuda_bf16.h>
#include <cstdint>
#include <math.h>

// ---------------------------------------------------------------------------
// Problem constants
// ---------------------------------------------------------------------------
#define NQ   64
#define MMQ  16
#define BB   8
#define KK   256
#define CC   512
#define K3   1536           // 3*CC for split-bf16 GEMMs
#define NROWS_Q 8192
#define NROWS_K 2048
#define BKP     2048
#define INV_EPS 20.0f
#define X_ELEMS (NROWS_Q*CC)

// ---------------------------------------------------------------------------
// Scratch (device globals; no allocation allowed)
// ---------------------------------------------------------------------------
__device__ __nv_bfloat16 g_xq3[NROWS_Q*K3];
__device__ __nv_bfloat16 g_xk3[NROWS_K*K3];
__device__ __nv_bfloat16 g_xv3[NROWS_K*K3];
__device__ __nv_bfloat16 g_wq3[CC*K3];
__device__ __nv_bfloat16 g_wk3[CC*K3];
__device__ __nv_bfloat16 g_wv3[CC*K3];
__device__ __nv_bfloat16 g_wp3[CC*K3];
__device__ float g_qlin[NROWS_Q*CC];
__device__ float g_klin[NROWS_K*CC];
__device__ float g_v   [NROWS_K*CC];
__device__ __nv_bfloat16 g_qr3[NROWS_Q*K3];
__device__ __nv_bfloat16 g_kn3[NROWS_K*K3];
__device__ float g_sim[BKP*MMQ*NQ];
__device__ float g_T  [BKP*MMQ*NQ];
__device__ __nv_bfloat16 g_Tt3[BB*1024*768];
__device__ __nv_bfloat16 g_vT3[BB*512*768];
__device__ __nv_bfloat16 g_y3[NROWS_Q*K3];

// ---------------------------------------------------------------------------
// PTX helpers
// ---------------------------------------------------------------------------
__device__ __forceinline__ uint32_t s2u(const void* p){
    uint32_t a;
    asm("{ .reg .u64 t; cvta.to.shared.u64 t, %1; cvt.u32.u64 %0, t; }"
        : "=r"(a) : "l"(p));
    return a;
}

#define CP_ASYNC16(dst, src) \
    asm volatile("cp.async.cg.shared.global [%0], [%1], 16;" :: "r"(dst), "l"(src) : "memory")
#define CP_COMMIT() asm volatile("cp.async.commit_group;" ::: "memory")
#define CP_WAIT1()  asm volatile("cp.async.wait_group 1;" ::: "memory")
#define CP_WAIT0()  asm volatile("cp.async.wait_group 0;" ::: "memory")

#define LDMATRIX_X4(r0, r1, r2, r3, addr) \
    asm volatile("ldmatrix.sync.aligned.m8n8.x4.shared.b16 {%0,%1,%2,%3}, [%4];" \
                 : "=r"(r0), "=r"(r1), "=r"(r2), "=r"(r3) : "r"(addr))

#define MMA16816(d, a, b0, b1) \
    asm volatile("mma.sync.aligned.m16n8k16.row.col.f32.bf16.bf16.f32 " \
                 "{%0,%1,%2,%3}, {%4,%5,%6,%7}, {%8,%9}, {%0,%1,%2,%3};" \
                 : "+f"((d)[0]), "+f"((d)[1]), "+f"((d)[2]), "+f"((d)[3]) \
                 : "r"((a)[0]), "r"((a)[1]), "r"((a)[2]), "r"((a)[3]), \
                   "r"(b0), "r"(b1))

__device__ __forceinline__ unsigned short bfr(__nv_bfloat16 h){
    return *reinterpret_cast<unsigned short*>(&h);
}
__device__ __forceinline__ void split_bf16(float x, __nv_bfloat16& h, __nv_bfloat16& l){
    h = __float2bfloat16(x);
    l = __float2bfloat16(x - __bfloat162float(h));
}
__device__ __forceinline__ uint32_t pack2(__nv_bfloat16 a, __nv_bfloat16 b){
    return (uint32_t)bfr(a) | ((uint32_t)bfr(b) << 16);
}

// ---------------------------------------------------------------------------
// HMMA GEMM core: C[M,N] = A(M,K')·B(N,K')ᵀ, K-major bf16, fp32 accum.
// CTA tile 128x128, BK=64, 3-stage cp.async ring, 8 warps (4m x 2n),
// warp tile 32x64; B fragments double-buffered across ks (software pipeline).
// EPI=0 plain fp32 store; EPI=1 out-proj scatter+bias; EPI=2 split-bf16 emit.
// ---------------------------------------------------------------------------
#define STG   32768
#define GSMEM (3*STG)

template<int EPI>
__device__ __forceinline__
void gemm_core(const __nv_bfloat16* __restrict__ A, const __nv_bfloat16* __restrict__ B,
               void* __restrict__ Cv, const float* __restrict__ bias,
               int Kp, int ldc, int mb, int nb, int bz, long cStride,
               char* smem)
{
    const int tid  = threadIdx.x;
    const int w    = tid >> 5;
    const int lane = tid & 31;
    const int wm   = (w & 3) * 32;
    const int wn   = (w >> 2) * 64;

    const uint32_t sbase = s2u(smem);
    const int NC = Kp >> 6;

    const int lrow = tid >> 1;
    const int lcg0 = (tid & 1) * 4;

    auto load_chunk = [&](int c, int s){
        const uint32_t st = sbase + s * STG;
        const __nv_bfloat16* Ag = A + (long)(mb + lrow) * Kp + c * 64 + lcg0 * 8;
        const __nv_bfloat16* Bg = B + (long)(nb + lrow) * Kp + c * 64 + lcg0 * 8;
        const uint32_t rbase = lrow * 128;
        const uint32_t sw    = (lrow & 7) << 4;
#pragma unroll
        for (int j = 0; j < 4; j++) {
            uint32_t off = rbase + (((lcg0 + j) << 4) ^ sw);
            CP_ASYNC16(st + off, Ag + j * 8);
            CP_ASYNC16(st + 16384 + off, Bg + j * 8);
        }
        CP_COMMIT();
    };

    float acc[2][8][4];
#pragma unroll
    for (int i = 0; i < 2; i++)
#pragma unroll
        for (int j = 0; j < 8; j++)
#pragma unroll
            for (int q = 0; q < 4; q++) acc[i][j][q] = 0.f;

    load_chunk(0, 0);
    load_chunk(1, 1);

    const int a_r  = lane & 15;
    const int a_kb = (lane & 16);
    const int b_r  = ((lane >> 4) << 3) + (lane & 7);
    const int b_kb = ((lane >> 3) & 1) << 4;

    int stage = 0;
    for (int c = 0; c < NC; c++) {
        if (c + 1 < NC) CP_WAIT1(); else CP_WAIT0();
        __syncthreads();

        // issue next chunk's loads first (stage freed at iteration c-1)
        if (c + 2 < NC) {
            int ns = stage + 2; if (ns >= 3) ns -= 3;
            load_chunk(c + 2, ns);
        }

        const uint32_t sa = sbase + stage * STG;
        const uint32_t sb = sa + 16384;

        // B-fragment double buffer across ks
        uint32_t br2[2][4][4];
#pragma unroll
        for (int nj = 0; nj < 4; nj++) {
            int row = wn + nj * 16 + b_r;
            uint32_t kb = (uint32_t)(b_kb) ^ ((row & 7) << 4);
            LDMATRIX_X4(br2[0][nj][0], br2[0][nj][1], br2[0][nj][2], br2[0][nj][3],
                        sb + row * 128 + kb);
        }
#pragma unroll
        for (int ks = 0; ks < 4; ks++) {
            const int cur = ks & 1;
            if (ks < 3) {
#pragma unroll
                for (int nj = 0; nj < 4; nj++) {
                    int row = wn + nj * 16 + b_r;
                    uint32_t kb = (uint32_t)((ks + 1) * 32 + b_kb) ^ ((row & 7) << 4);
                    LDMATRIX_X4(br2[cur ^ 1][nj][0], br2[cur ^ 1][nj][1],
                                br2[cur ^ 1][nj][2], br2[cur ^ 1][nj][3],
                                sb + row * 128 + kb);
                }
            }
            uint32_t ar[2][4];
#pragma unroll
            for (int mi = 0; mi < 2; mi++) {
                int row = wm + mi * 16 + a_r;
                uint32_t kb = (uint32_t)(ks * 32 + a_kb) ^ ((row & 7) << 4);
                LDMATRIX_X4(ar[mi][0], ar[mi][1], ar[mi][2], ar[mi][3],
                            sa + row * 128 + kb);
            }
#pragma unroll
            for (int mi = 0; mi < 2; mi++)
#pragma unroll
                for (int nj = 0; nj < 4; nj++) {
                    MMA16816(acc[mi][nj * 2],     ar[mi], br2[cur][nj][0], br2[cur][nj][1]);
                    MMA16816(acc[mi][nj * 2 + 1], ar[mi], br2[cur][nj][2], br2[cur][nj][3]);
                }
        }
        stage++; if (stage == 3) stage = 0;
    }

    // ---- epilogue ----
    const int er = lane >> 2;
    const int ec = (lane & 3) * 2;
#pragma unroll
    for (int mi = 0; mi < 2; mi++) {
#pragma unroll
        for (int half = 0; half < 2; half++) {
            const int R = mb + wm + mi * 16 + er + half * 8;
            if (EPI == 0) {
                float* Crow = (float*)Cv + bz * cStride + (long)R * ldc;
#pragma unroll
                for (int nj = 0; nj < 8; nj++) {
                    const int col = nb + wn + nj * 8 + ec;
                    *(float2*)&Crow[col] =
                        make_float2(acc[mi][nj][half * 2], acc[mi][nj][half * 2 + 1]);
                }
            } else if (EPI == 1) {
                const int b2 = R >> 10, j = R & 1023, mq = j >> 6, nq = j & 63;
                float* Crow = (float*)Cv + (long)(((nq << 4) + mq) * 8 + b2) * CC;
#pragma unroll
                for (int nj = 0; nj < 8; nj++) {
                    const int col = nb + wn + nj * 8 + ec;
                    *(float2*)&Crow[col] = make_float2(
                        acc[mi][nj][half * 2] + bias[col],
                        acc[mi][nj][half * 2 + 1] + bias[col + 1]);
                }
            } else {
                __nv_bfloat16* Yr = (__nv_bfloat16*)Cv + bz * cStride + (long)R * K3;
#pragma unroll
                for (int nj = 0; nj < 8; nj++) {
                    const int col = nb + wn + nj * 8 + ec;
                    __nv_bfloat16 h0, l0, h1, l1;
                    split_bf16(acc[mi][nj][half * 2],     h0, l0);
                    split_bf16(acc[mi][nj][half * 2 + 1], h1, l1);
                    uint32_t hp = pack2(h0, h1), lp = pack2(l0, l1);
                    *(uint32_t*)&Yr[col]        = hp;
                    *(uint32_t*)&Yr[col + CC]   = lp;
                    *(uint32_t*)&Yr[col + 2*CC] = hp;
                }
            }
        }
    }
}

template<int EPI>
__global__ __launch_bounds__(256, 2)
void hgemm(const __nv_bfloat16* __restrict__ A, const __nv_bfloat16* __restrict__ B,
           void* __restrict__ C, const float* __restrict__ bias,
           int Kp, int ldc, long aStride, long bStride, long cStride)
{
    extern __shared__ char smem[];
    const int bz = blockIdx.z;
    gemm_core<EPI>(A + bz * aStride, B + bz * bStride, C, bias,
                   Kp, ldc, blockIdx.y * 128, blockIdx.x * 128, bz, cStride, smem);
}

// Fused q/k/v projection: grid.y in [0,96): 0-63 q, 64-79 k, 80-95 v
__global__ __launch_bounds__(256, 2)
void hgemm_proj(const __nv_bfloat16* __restrict__ Aq, const __nv_bfloat16* __restrict__ Bq,
                float* __restrict__ Cq,
                const __nv_bfloat16* __restrict__ Ak, const __nv_bfloat16* __restrict__ Bk,
                float* __restrict__ Ck,
                const __nv_bfloat16* __restrict__ Av, const __nv_bfloat16* __restrict__ Bv,
                float* __restrict__ Cv)
{
    extern __shared__ char smem[];
    const int by = blockIdx.y;
    const __nv_bfloat16 *A, *B;
    float* C;
    int mb;
    if (by < 64)      { A = Aq; B = Bq; C = Cq; mb = by * 128; }
    else if (by < 80) { A = Ak; B = Bk; C = Ck; mb = (by - 64) * 128; }
    else              { A = Av; B = Bv; C = Cv; mb = (by - 80) * 128; }
    gemm_core<0>(A, B, C, nullptr, K3, CC, mb, blockIdx.x * 128, 0, 0, smem);
}

// ---------------------------------------------------------------------------
// conv3 helpers
// ---------------------------------------------------------------------------
__device__ __forceinline__ void conv3_row(const float* __restrict__ in,
                                          __nv_bfloat16* __restrict__ out,
                                          int t, int mode)
{
    float4 v = ((const float4*)in)[t];
    __nv_bfloat16 h0,h1,h2,h3,l0,l1,l2,l3;
    split_bf16(v.x,h0,l0); split_bf16(v.y,h1,l1);
    split_bf16(v.z,h2,l2); split_bf16(v.w,h3,l3);
    ushort4 hp = make_ushort4(bfr(h0),bfr(h1),bfr(h2),bfr(h3));
    ushort4 lp = make_ushort4(bfr(l0),bfr(l1),bfr(l2),bfr(l3));
    ((ushort4*)(out))[t]        = hp;
    ((ushort4*)(out + CC))[t]   = mode ? hp : lp;
    ((ushort4*)(out + 2*CC))[t] = mode ? lp : hp;
}

__global__ void conv3_weights(const float* __restrict__ w0, __nv_bfloat16* __restrict__ o0,
                              const float* __restrict__ w1, __nv_bfloat16* __restrict__ o1,
                              const float* __restrict__ w2, __nv_bfloat16* __restrict__ o2,
                              const float* __restrict__ w3, __nv_bfloat16* __restrict__ o3)
{
    const int r = blockIdx.x;
    const int sel = r >> 9, rw = r & 511;
    const float* in; __nv_bfloat16* out;
    if (sel == 0)      { in = w0; out = o0; }
    else if (sel == 1) { in = w1; out = o1; }
    else if (sel == 2) { in = w2; out = o2; }
    else               { in = w3; out = o3; }
    conv3_row(in + (long)rw * CC, out + (long)rw * K3, threadIdx.x, 1);
}

__global__ void conv3_acts(const float* __restrict__ xq, __nv_bfloat16* __restrict__ oq,
                           const float* __restrict__ xk, __nv_bfloat16* __restrict__ ok,
                           const float* __restrict__ xv, __nv_bfloat16* __restrict__ ov)
{
    const int r = blockIdx.x;       // 0..12287
    const float* in; __nv_bfloat16* out; int rr;
    if (r < 8192)       { in = xq; out = oq; rr = r; }
    else if (r < 10240) { in = xk; out = ok; rr = r - 8192; }
    else                { in = xv; out = ov; rr = r - 10240; }
    conv3_row(in + (long)rr * CC, out + (long)rr * K3, threadIdx.x, 0);
}

// ---------------------------------------------------------------------------
// Fused norm: rows <8192 = q (reorder + MODE1), else k (MODE0).
// ---------------------------------------------------------------------------
__global__ void norm_fused(const float* __restrict__ qin, __nv_bfloat16* __restrict__ qout,
                           const float* __restrict__ kin, __nv_bfloat16* __restrict__ kout)
{
    const int r = blockIdx.x;
    const int t = threadIdx.x;
    const float* in;
    __nv_bfloat16* out;
    long orow;
    int mode;
    if (r < NROWS_Q) {
        in = qin + (long)r * CC;
        int n = r >> 7, m = (r >> 3) & 15, b = r & 7;
        orow = (long)(b * 1024 + m * 64 + n);
        out = qout; mode = 1;
    } else {
        int rk = r - NROWS_Q;
        in = kin + (long)rk * CC;
        orow = rk;
        out = kout; mode = 0;
    }
    float4 v = ((const float4*)in)[t];
    float ss = v.x*v.x + v.y*v.y + v.z*v.z + v.w*v.w;
#pragma unroll
    for (int o = 16; o; o >>= 1) ss += __shfl_xor_sync(0xffffffffu, ss, o);
    __shared__ float sw[4];
    if ((t & 31) == 0) sw[t >> 5] = ss;
    __syncthreads();
    float tot = sw[0] + sw[1] + sw[2] + sw[3];
    float scale = 1.0f / fmaxf(sqrtf(tot), 1e-12f);

    __nv_bfloat16 h0,h1,h2,h3,l0,l1,l2,l3;
    split_bf16(v.x*scale,h0,l0); split_bf16(v.y*scale,h1,l1);
    split_bf16(v.z*scale,h2,l2); split_bf16(v.w*scale,h3,l3);
    ushort4 hp = make_ushort4(bfr(h0),bfr(h1),bfr(h2),bfr(h3));
    ushort4 lp = make_ushort4(bfr(l0),bfr(l1),bfr(l2),bfr(l3));
    __nv_bfloat16* base = out + orow * K3;
    ((ushort4*)(base))[t]        = hp;
    ((ushort4*)(base + CC))[t]   = mode ? hp : lp;
    ((ushort4*)(base + 2*CC))[t] = mode ? lp : hp;
}

// ---------------------------------------------------------------------------
// Transpose + split-convert: in fp32 [b][256][W] -> out bf16 [b][W][768]
// ---------------------------------------------------------------------------
template<int MODE>
__global__ void trconv_kernel(const float* __restrict__ in, __nv_bfloat16* __restrict__ out, int W)
{
    __shared__ float s[32][33];
    const int b = blockIdx.z;
    const float* ib = in + (long)b * 256 * W;
    __nv_bfloat16* ob = out + (long)b * W * 768;
    const int k0 = blockIdx.y * 32, w0 = blockIdx.x * 32;
    const int tx = threadIdx.x, ty = threadIdx.y;
#pragma unroll
    for (int i = 0; i < 4; i++)
        s[ty + 8*i][tx] = ib[(long)(k0 + ty + 8*i) * W + w0 + tx];
    __syncthreads();
#pragma unroll
    for (int i = 0; i < 4; i++) {
        const int wrow = w0 + ty + 8*i;
        float x = s[tx][ty + 8*i];
        __nv_bfloat16 h, l; split_bf16(x, h, l);
        __nv_bfloat16* p = ob + (long)wrow * 768 + k0 + tx;
        p[0]   = h;
        p[256] = MODE ? h : l;
        p[512] = MODE ? l : h;
    }
}

// ---------------------------------------------------------------------------
// Sinkhorn (validated): one warp per (b,k) problem, scaling-domain.
// ---------------------------------------------------------------------------
__global__ __launch_bounds__(256)
void sinkhorn_kernel(const float* __restrict__ sim, float* __restrict__ T,
                     float* __restrict__ score)
{
    const int p    = blockIdx.x * 8 + (threadIdx.x >> 5);
    const int lane = threadIdx.x & 31;
    const float* srow = sim + (long)p * (MMQ * NQ);

    float Km[32];
#pragma unroll
    for (int i = 0; i < 16; i++) {
        Km[i]      = __expf((srow[i * 64 + lane]      - 1.0f) * INV_EPS);
        Km[i + 16] = __expf((srow[i * 64 + lane + 32] - 1.0f) * INV_EPS);
    }

    const float MU = 1.0f / 16.0f + 1e-8f;
    const float NU = 1.0f / 64.0f + 1e-8f;
    float b0 = 1.0f, b1 = 1.0f;
    float a[16];

#pragma unroll 1
    for (int iter = 0; iter < 100; iter++) {
        float v[16];
#pragma unroll
        for (int i = 0; i < 16; i++) v[i] = Km[i] * b0 + Km[i + 16] * b1;
#pragma unroll
        for (int i = 0; i < 16; i++) v[i] += __shfl_xor_sync(0xffffffffu, v[i], 16);
#pragma unroll
        for (int i = 0; i < 8; i++) {
            float t0 = v[i], t1 = v[i + 8];
            float r0 = __shfl_xor_sync(0xffffffffu, t0, 8);
            float r1 = __shfl_xor_sync(0xffffffffu, t1, 8);
            v[i] = (lane & 8) ? (t1 + r1) : (t0 + r0);
        }
#pragma unroll
        for (int i = 0; i < 4; i++) {
            float t0 = v[i], t1 = v[i + 4];
            float r0 = __shfl_xor_sync(0xffffffffu, t0, 4);
            float r1 = __shfl_xor_sync(0xffffffffu, t1, 4);
            v[i] = (lane & 4) ? (t1 + r1) : (t0 + r0);
        }
#pragma unroll
        for (int i = 0; i < 2; i++) {
            float t0 = v[i], t1 = v[i + 2];
            float r0 = __shfl_xor_sync(0xffffffffu, t0, 2);
            float r1 = __shfl_xor_sync(0xffffffffu, t1, 2);
            v[i] = (lane & 2) ? (t1 + r1) : (t0 + r0);
        }
        {
            float t0 = v[0], t1 = v[1];
            float r0 = __shfl_xor_sync(0xffffffffu, t0, 1);
            float r1 = __shfl_xor_sync(0xffffffffu, t1, 1);
            v[0] = (lane & 1) ? (t1 + r1) : (t0 + r0);
        }
        float av = __fdividef(MU, v[0]);
#pragma unroll
        for (int i = 0; i < 16; i++) a[i] = __shfl_sync(0xffffffffu, av, i);

        float c0a = 0.f, c0b = 0.f, c1a = 0.f, c1b = 0.f;
#pragma unroll
        for (int i = 0; i < 16; i += 2) {
            c0a += Km[i] * a[i];       c0b += Km[i + 1] * a[i + 1];
            c1a += Km[i + 16] * a[i];  c1b += Km[i + 17] * a[i + 1];
        }
        b0 = __fdividef(NU, c0a + c0b);
        b1 = __fdividef(NU, c1a + c1b);
    }

    float* Trow = T + (long)p * (MMQ * NQ);
    float* Srow = score + (long)p * (MMQ * NQ);
#pragma unroll
    for (int i = 0; i < 16; i++) {
        float T0 = a[i] * Km[i] * b0;
        float T1 = a[i] * Km[i + 16] * b1;
        Trow[i * 64 + lane]      = T0;
        Trow[i * 64 + lane + 32] = T1;
        Srow[i * 64 + lane]      = 1024.0f * srow[i * 64 + lane] * T0;
        Srow[i * 64 + lane + 32] = 1024.0f * srow[i * 64 + lane + 32] * T1;
    }
}

// ---------------------------------------------------------------------------
extern "C" void kernel_launch(void* const* d_in, const int* in_sizes, int n_in,
                              void* d_out, int out_size)
{
    const float* xq = (const float*)d_in[0];
    const float* xk = (const float*)d_in[1];
    const float* xv = (const float*)d_in[2];
    const float* Wq = (const float*)d_in[3];
    const float* Wk = (const float*)d_in[4];
    const float* Wv = (const float*)d_in[5];
    const float* Wp = (const float*)d_in[6];
    const float* bp = (const float*)d_in[7];
    float* out_x     = (float*)d_out;
    float* out_score = out_x + X_ELEMS;

    __nv_bfloat16 *xq3,*xk3,*xv3,*wq3,*wk3,*wv3,*wp3,*qr3,*kn3,*Tt3,*vT3,*y3;
    float *qlin,*klin,*vbuf,*sim,*T;
    cudaGetSymbolAddress((void**)&xq3, g_xq3);
    cudaGetSymbolAddress((void**)&xk3, g_xk3);
    cudaGetSymbolAddress((void**)&xv3, g_xv3);
    cudaGetSymbolAddress((void**)&wq3, g_wq3);
    cudaGetSymbolAddress((void**)&wk3, g_wk3);
    cudaGetSymbolAddress((void**)&wv3, g_wv3);
    cudaGetSymbolAddress((void**)&wp3, g_wp3);
    cudaGetSymbolAddress((void**)&qr3, g_qr3);
    cudaGetSymbolAddress((void**)&kn3, g_kn3);
    cudaGetSymbolAddress((void**)&Tt3, g_Tt3);
    cudaGetSymbolAddress((void**)&vT3, g_vT3);
    cudaGetSymbolAddress((void**)&y3,  g_y3);
    cudaGetSymbolAddress((void**)&qlin, g_qlin);
    cudaGetSymbolAddress((void**)&klin, g_klin);
    cudaGetSymbolAddress((void**)&vbuf, g_v);
    cudaGetSymbolAddress((void**)&sim,  g_sim);
    cudaGetSymbolAddress((void**)&T,    g_T);

    cudaFuncSetAttribute(hgemm<0>,   cudaFuncAttributeMaxDynamicSharedMemorySize, GSMEM);
    cudaFuncSetAttribute(hgemm<1>,   cudaFuncAttributeMaxDynamicSharedMemorySize, GSMEM);
    cudaFuncSetAttribute(hgemm<2>,   cudaFuncAttributeMaxDynamicSharedMemorySize, GSMEM);
    cudaFuncSetAttribute(hgemm_proj, cudaFuncAttributeMaxDynamicSharedMemorySize, GSMEM);

    // Side stream + events for fork/join (host objects; graph replays skip host code)
    cudaStream_t sA;
    cudaStreamCreateWithFlags(&sA, cudaStreamNonBlocking);
    cudaEvent_t eRoot, eActs, eProj, eV;
    cudaEventCreateWithFlags(&eRoot, cudaEventDisableTiming);
    cudaEventCreateWithFlags(&eActs, cudaEventDisableTiming);
    cudaEventCreateWithFlags(&eProj, cudaEventDisableTiming);
    cudaEventCreateWithFlags(&eV,    cudaEventDisableTiming);

    // --- fork: weights conv (main) || acts conv (sA) ---
    cudaEventRecord(eRoot, 0);
    conv3_weights<<<4 * CC, 128>>>(Wq, wq3, Wk, wk3, Wv, wv3, Wp, wp3);
    cudaStreamWaitEvent(sA, eRoot, 0);
    conv3_acts<<<12288, 128, 0, sA>>>(xq, xq3, xk, xk3, xv, xv3);
    cudaEventRecord(eActs, sA);
    cudaStreamWaitEvent(0, eActs, 0);

    // --- q/k/v projections: single fused launch ---
    hgemm_proj<<<dim3(4, 96, 1), 256, GSMEM>>>(
        xq3, wq3, qlin, xk3, wk3, klin, xv3, wv3, vbuf);
    cudaEventRecord(eProj, 0);

    // --- fork: v transpose (sA) overlaps norm + sim + sinkhorn (main) ---
    cudaStreamWaitEvent(sA, eProj, 0);
    trconv_kernel<1><<<dim3(16, 8, 8), dim3(32, 8), 0, sA>>>(vbuf, vT3, 512);
    cudaEventRecord(eV, sA);

    // --- main: l2 normalize (fused q+k) ---
    norm_fused<<<NROWS_Q + NROWS_K, 128>>>(qlin, qr3, klin, kn3);

    // --- sim[b][k][m*64+n] (fp32) ---
    hgemm<0><<<dim3(8, 2, 8), 256, GSMEM>>>(
        kn3, qr3, sim, nullptr, K3, 1024,
        (long)256 * K3, (long)1024 * K3, (long)256 * 1024);

    // --- Sinkhorn -> T + score_map ---
    sinkhorn_kernel<<<BKP / 8, 256>>>(sim, T, out_score);

    // --- T transpose ---
    trconv_kernel<0><<<dim3(32, 8, 8), dim3(32, 8)>>>(T, Tt3, 1024);

    // --- join v path, then attn·v with fused split-bf16 epilogue ---
    cudaStreamWaitEvent(0, eV, 0);
    hgemm<2><<<dim3(4, 8, 8), 256, GSMEM>>>(
        Tt3, vT3, y3, nullptr, 768, 0,
        (long)1024 * 768, (long)512 * 768, (long)1024 * K3);

    // --- out projection + bias + scatter to (n,m,b,c) ---
    hgemm<1><<<dim3(4, 64, 1), 256, GSMEM>>>(
        y3, wp3, out_x, bp, K3, CC, 0, 0, 0);
}

// round 6
// speedup vs baseline: 2.4209x; 1.1392x over previous
#include <cuda_runtime.h>
#include <cuda_bf16.h>
#include <cstdint>
#include <math.h>

// ---------------------------------------------------------------------------
// Problem constants
// ---------------------------------------------------------------------------
#define NQ   64
#define MMQ  16
#define BB   8
#define KK   256
#define CC   512
#define K3   1536           // 3*CC for split-bf16 GEMMs
#define NROWS_Q 8192
#define NROWS_K 2048
#define BKP     2048
#define INV_EPS 20.0f
#define X_ELEMS (NROWS_Q*CC)

// ---------------------------------------------------------------------------
// Scratch (device globals; no allocation allowed)
// ---------------------------------------------------------------------------
__device__ __nv_bfloat16 g_xq3[NROWS_Q*K3];
__device__ __nv_bfloat16 g_xk3[NROWS_K*K3];
__device__ __nv_bfloat16 g_xv3[NROWS_K*K3];
__device__ __nv_bfloat16 g_wq3[CC*K3];
__device__ __nv_bfloat16 g_wk3[CC*K3];
__device__ __nv_bfloat16 g_wv3[CC*K3];
__device__ __nv_bfloat16 g_wp3[CC*K3];
__device__ float g_qlin[NROWS_Q*CC];
__device__ float g_klin[NROWS_K*CC];
__device__ float g_v   [NROWS_K*CC];          // vp = v @ Wp^T (fp32)
__device__ __nv_bfloat16 g_qr3[NROWS_Q*K3];
__device__ __nv_bfloat16 g_kn3[NROWS_K*K3];
__device__ float g_sim[BKP*MMQ*NQ];
__device__ float g_T  [BKP*MMQ*NQ];
__device__ __nv_bfloat16 g_Tt3[BB*1024*768];
__device__ __nv_bfloat16 g_vT3[BB*512*768];
__device__ __nv_bfloat16 g_v3[NROWS_K*K3];    // split-bf16 v (A-mode)

// ---------------------------------------------------------------------------
// PTX helpers
// ---------------------------------------------------------------------------
__device__ __forceinline__ uint32_t s2u(const void* p){
    uint32_t a;
    asm("{ .reg .u64 t; cvta.to.shared.u64 t, %1; cvt.u32.u64 %0, t; }"
        : "=r"(a) : "l"(p));
    return a;
}

#define CP_ASYNC16(dst, src) \
    asm volatile("cp.async.cg.shared.global [%0], [%1], 16;" :: "r"(dst), "l"(src) : "memory")
#define CP_COMMIT() asm volatile("cp.async.commit_group;" ::: "memory")
#define CP_WAIT1()  asm volatile("cp.async.wait_group 1;" ::: "memory")
#define CP_WAIT0()  asm volatile("cp.async.wait_group 0;" ::: "memory")

#define LDMATRIX_X4(r0, r1, r2, r3, addr) \
    asm volatile("ldmatrix.sync.aligned.m8n8.x4.shared.b16 {%0,%1,%2,%3}, [%4];" \
                 : "=r"(r0), "=r"(r1), "=r"(r2), "=r"(r3) : "r"(addr))

#define MMA16816(d, a, b0, b1) \
    asm volatile("mma.sync.aligned.m16n8k16.row.col.f32.bf16.bf16.f32 " \
                 "{%0,%1,%2,%3}, {%4,%5,%6,%7}, {%8,%9}, {%0,%1,%2,%3};" \
                 : "+f"((d)[0]), "+f"((d)[1]), "+f"((d)[2]), "+f"((d)[3]) \
                 : "r"((a)[0]), "r"((a)[1]), "r"((a)[2]), "r"((a)[3]), \
                   "r"(b0), "r"(b1))

__device__ __forceinline__ unsigned short bfr(__nv_bfloat16 h){
    return *reinterpret_cast<unsigned short*>(&h);
}
__device__ __forceinline__ void split_bf16(float x, __nv_bfloat16& h, __nv_bfloat16& l){
    h = __float2bfloat16(x);
    l = __float2bfloat16(x - __bfloat162float(h));
}
__device__ __forceinline__ uint32_t pack2(__nv_bfloat16 a, __nv_bfloat16 b){
    return (uint32_t)bfr(a) | ((uint32_t)bfr(b) << 16);
}

// ---------------------------------------------------------------------------
// HMMA GEMM core: C[M,N] = A(M,K')·B(N,K')ᵀ, K-major bf16, fp32 accum.
// CTA tile 128x128, BK=64, 3-stage cp.async ring, 8 warps (4m x 2n).
// EPI=0 plain fp32 store; EPI=2 split-bf16 A-mode emit;
// EPI=3 batched out scatter+bias: row R (0..1023) of batch bz ->
//       out[((nq*16+mq)*8+bz)][c], nq=R&63, mq=R>>6.
// ---------------------------------------------------------------------------
#define STG   32768
#define GSMEM (3*STG)

template<int EPI>
__device__ __forceinline__
void gemm_core(const __nv_bfloat16* __restrict__ A, const __nv_bfloat16* __restrict__ B,
               void* __restrict__ Cv, const float* __restrict__ bias,
               int Kp, int ldc, int mb, int nb, int bz, long cStride,
               char* smem)
{
    const int tid  = threadIdx.x;
    const int w    = tid >> 5;
    const int lane = tid & 31;
    const int wm   = (w & 3) * 32;
    const int wn   = (w >> 2) * 64;

    const uint32_t sbase = s2u(smem);
    const int NC = Kp >> 6;

    const int lrow = tid >> 1;
    const int lcg0 = (tid & 1) * 4;

    auto load_chunk = [&](int c, int s){
        const uint32_t st = sbase + s * STG;
        const __nv_bfloat16* Ag = A + (long)(mb + lrow) * Kp + c * 64 + lcg0 * 8;
        const __nv_bfloat16* Bg = B + (long)(nb + lrow) * Kp + c * 64 + lcg0 * 8;
        const uint32_t rbase = lrow * 128;
        const uint32_t sw    = (lrow & 7) << 4;
#pragma unroll
        for (int j = 0; j < 4; j++) {
            uint32_t off = rbase + (((lcg0 + j) << 4) ^ sw);
            CP_ASYNC16(st + off, Ag + j * 8);
            CP_ASYNC16(st + 16384 + off, Bg + j * 8);
        }
        CP_COMMIT();
    };

    float acc[2][8][4];
#pragma unroll
    for (int i = 0; i < 2; i++)
#pragma unroll
        for (int j = 0; j < 8; j++)
#pragma unroll
            for (int q = 0; q < 4; q++) acc[i][j][q] = 0.f;

    load_chunk(0, 0);
    load_chunk(1, 1);

    const int a_r  = lane & 15;
    const int a_kb = (lane & 16);
    const int b_r  = ((lane >> 4) << 3) + (lane & 7);
    const int b_kb = ((lane >> 3) & 1) << 4;

    int stage = 0;
    for (int c = 0; c < NC; c++) {
        if (c + 1 < NC) CP_WAIT1(); else CP_WAIT0();
        __syncthreads();

        if (c + 2 < NC) {
            int ns = stage + 2; if (ns >= 3) ns -= 3;
            load_chunk(c + 2, ns);
        }

        const uint32_t sa = sbase + stage * STG;
        const uint32_t sb = sa + 16384;

        uint32_t br2[2][4][4];
#pragma unroll
        for (int nj = 0; nj < 4; nj++) {
            int row = wn + nj * 16 + b_r;
            uint32_t kb = (uint32_t)(b_kb) ^ ((row & 7) << 4);
            LDMATRIX_X4(br2[0][nj][0], br2[0][nj][1], br2[0][nj][2], br2[0][nj][3],
                        sb + row * 128 + kb);
        }
#pragma unroll
        for (int ks = 0; ks < 4; ks++) {
            const int cur = ks & 1;
            if (ks < 3) {
#pragma unroll
                for (int nj = 0; nj < 4; nj++) {
                    int row = wn + nj * 16 + b_r;
                    uint32_t kb = (uint32_t)((ks + 1) * 32 + b_kb) ^ ((row & 7) << 4);
                    LDMATRIX_X4(br2[cur ^ 1][nj][0], br2[cur ^ 1][nj][1],
                                br2[cur ^ 1][nj][2], br2[cur ^ 1][nj][3],
                                sb + row * 128 + kb);
                }
            }
            uint32_t ar[2][4];
#pragma unroll
            for (int mi = 0; mi < 2; mi++) {
                int row = wm + mi * 16 + a_r;
                uint32_t kb = (uint32_t)(ks * 32 + a_kb) ^ ((row & 7) << 4);
                LDMATRIX_X4(ar[mi][0], ar[mi][1], ar[mi][2], ar[mi][3],
                            sa + row * 128 + kb);
            }
#pragma unroll
            for (int mi = 0; mi < 2; mi++)
#pragma unroll
                for (int nj = 0; nj < 4; nj++) {
                    MMA16816(acc[mi][nj * 2],     ar[mi], br2[cur][nj][0], br2[cur][nj][1]);
                    MMA16816(acc[mi][nj * 2 + 1], ar[mi], br2[cur][nj][2], br2[cur][nj][3]);
                }
        }
        stage++; if (stage == 3) stage = 0;
    }

    // ---- epilogue ----
    const int er = lane >> 2;
    const int ec = (lane & 3) * 2;
#pragma unroll
    for (int mi = 0; mi < 2; mi++) {
#pragma unroll
        for (int half = 0; half < 2; half++) {
            const int R = mb + wm + mi * 16 + er + half * 8;
            if (EPI == 0) {
                float* Crow = (float*)Cv + bz * cStride + (long)R * ldc;
#pragma unroll
                for (int nj = 0; nj < 8; nj++) {
                    const int col = nb + wn + nj * 8 + ec;
                    *(float2*)&Crow[col] =
                        make_float2(acc[mi][nj][half * 2], acc[mi][nj][half * 2 + 1]);
                }
            } else if (EPI == 3) {
                const int mq = R >> 6, nq = R & 63;
                float* Crow = (float*)Cv + (long)(((nq << 4) + mq) * 8 + bz) * CC;
#pragma unroll
                for (int nj = 0; nj < 8; nj++) {
                    const int col = nb + wn + nj * 8 + ec;
                    *(float2*)&Crow[col] = make_float2(
                        acc[mi][nj][half * 2] + bias[col],
                        acc[mi][nj][half * 2 + 1] + bias[col + 1]);
                }
            } else {
                // EPI==2: split-bf16 A-mode emit [hi|lo|hi]
                __nv_bfloat16* Yr = (__nv_bfloat16*)Cv + bz * cStride + (long)R * K3;
#pragma unroll
                for (int nj = 0; nj < 8; nj++) {
                    const int col = nb + wn + nj * 8 + ec;
                    __nv_bfloat16 h0, l0, h1, l1;
                    split_bf16(acc[mi][nj][half * 2],     h0, l0);
                    split_bf16(acc[mi][nj][half * 2 + 1], h1, l1);
                    uint32_t hp = pack2(h0, h1), lp = pack2(l0, l1);
                    *(uint32_t*)&Yr[col]        = hp;
                    *(uint32_t*)&Yr[col + CC]   = lp;
                    *(uint32_t*)&Yr[col + 2*CC] = hp;
                }
            }
        }
    }
}

template<int EPI>
__global__ __launch_bounds__(256, 2)
void hgemm(const __nv_bfloat16* __restrict__ A, const __nv_bfloat16* __restrict__ B,
           void* __restrict__ C, const float* __restrict__ bias,
           int Kp, int ldc, long aStride, long bStride, long cStride)
{
    extern __shared__ char smem[];
    const int bz = blockIdx.z;
    gemm_core<EPI>(A + bz * aStride, B + bz * bStride, C, bias,
                   Kp, ldc, blockIdx.y * 128, blockIdx.x * 128, bz, cStride, smem);
}

// Fused q/k/v projection: grid.y in [0,96): 0-63 q, 64-79 k (fp32 out),
// 80-95 v (split-bf16 emit for the vp GEMM).
__global__ __launch_bounds__(256, 2)
void hgemm_proj(const __nv_bfloat16* __restrict__ Aq, const __nv_bfloat16* __restrict__ Bq,
                float* __restrict__ Cq,
                const __nv_bfloat16* __restrict__ Ak, const __nv_bfloat16* __restrict__ Bk,
                float* __restrict__ Ck,
                const __nv_bfloat16* __restrict__ Av, const __nv_bfloat16* __restrict__ Bv,
                __nv_bfloat16* __restrict__ Cv3)
{
    extern __shared__ char smem[];
    const int by = blockIdx.y;
    if (by < 64) {
        gemm_core<0>(Aq, Bq, Cq, nullptr, K3, CC, by * 128, blockIdx.x * 128, 0, 0, smem);
    } else if (by < 80) {
        gemm_core<0>(Ak, Bk, Ck, nullptr, K3, CC, (by - 64) * 128, blockIdx.x * 128, 0, 0, smem);
    } else {
        gemm_core<2>(Av, Bv, Cv3, nullptr, K3, 0, (by - 80) * 128, blockIdx.x * 128, 0, 0, smem);
    }
}

// ---------------------------------------------------------------------------
// conv3 helpers
// ---------------------------------------------------------------------------
__device__ __forceinline__ void conv3_row(const float* __restrict__ in,
                                          __nv_bfloat16* __restrict__ out,
                                          int t, int mode)
{
    float4 v = ((const float4*)in)[t];
    __nv_bfloat16 h0,h1,h2,h3,l0,l1,l2,l3;
    split_bf16(v.x,h0,l0); split_bf16(v.y,h1,l1);
    split_bf16(v.z,h2,l2); split_bf16(v.w,h3,l3);
    ushort4 hp = make_ushort4(bfr(h0),bfr(h1),bfr(h2),bfr(h3));
    ushort4 lp = make_ushort4(bfr(l0),bfr(l1),bfr(l2),bfr(l3));
    ((ushort4*)(out))[t]        = hp;
    ((ushort4*)(out + CC))[t]   = mode ? hp : lp;
    ((ushort4*)(out + 2*CC))[t] = mode ? lp : hp;
}

__global__ void conv3_weights(const float* __restrict__ w0, __nv_bfloat16* __restrict__ o0,
                              const float* __restrict__ w1, __nv_bfloat16* __restrict__ o1,
                              const float* __restrict__ w2, __nv_bfloat16* __restrict__ o2,
                              const float* __restrict__ w3, __nv_bfloat16* __restrict__ o3)
{
    const int r = blockIdx.x;
    const int sel = r >> 9, rw = r & 511;
    const float* in; __nv_bfloat16* out;
    if (sel == 0)      { in = w0; out = o0; }
    else if (sel == 1) { in = w1; out = o1; }
    else if (sel == 2) { in = w2; out = o2; }
    else               { in = w3; out = o3; }
    conv3_row(in + (long)rw * CC, out + (long)rw * K3, threadIdx.x, 1);
}

__global__ void conv3_acts(const float* __restrict__ xq, __nv_bfloat16* __restrict__ oq,
                           const float* __restrict__ xk, __nv_bfloat16* __restrict__ ok,
                           const float* __restrict__ xv, __nv_bfloat16* __restrict__ ov)
{
    const int r = blockIdx.x;       // 0..12287
    const float* in; __nv_bfloat16* out; int rr;
    if (r < 8192)       { in = xq; out = oq; rr = r; }
    else if (r < 10240) { in = xk; out = ok; rr = r - 8192; }
    else                { in = xv; out = ov; rr = r - 10240; }
    conv3_row(in + (long)rr * CC, out + (long)rr * K3, threadIdx.x, 0);
}

// ---------------------------------------------------------------------------
// Fused norm: rows <8192 = q (reorder + MODE1), else k (MODE0).
// ---------------------------------------------------------------------------
__global__ void norm_fused(const float* __restrict__ qin, __nv_bfloat16* __restrict__ qout,
                           const float* __restrict__ kin, __nv_bfloat16* __restrict__ kout)
{
    const int r = blockIdx.x;
    const int t = threadIdx.x;
    const float* in;
    __nv_bfloat16* out;
    long orow;
    int mode;
    if (r < NROWS_Q) {
        in = qin + (long)r * CC;
        int n = r >> 7, m = (r >> 3) & 15, b = r & 7;
        orow = (long)(b * 1024 + m * 64 + n);
        out = qout; mode = 1;
    } else {
        int rk = r - NROWS_Q;
        in = kin + (long)rk * CC;
        orow = rk;
        out = kout; mode = 0;
    }
    float4 v = ((const float4*)in)[t];
    float ss = v.x*v.x + v.y*v.y + v.z*v.z + v.w*v.w;
#pragma unroll
    for (int o = 16; o; o >>= 1) ss += __shfl_xor_sync(0xffffffffu, ss, o);
    __shared__ float sw[4];
    if ((t & 31) == 0) sw[t >> 5] = ss;
    __syncthreads();
    float tot = sw[0] + sw[1] + sw[2] + sw[3];
    float scale = 1.0f / fmaxf(sqrtf(tot), 1e-12f);

    __nv_bfloat16 h0,h1,h2,h3,l0,l1,l2,l3;
    split_bf16(v.x*scale,h0,l0); split_bf16(v.y*scale,h1,l1);
    split_bf16(v.z*scale,h2,l2); split_bf16(v.w*scale,h3,l3);
    ushort4 hp = make_ushort4(bfr(h0),bfr(h1),bfr(h2),bfr(h3));
    ushort4 lp = make_ushort4(bfr(l0),bfr(l1),bfr(l2),bfr(l3));
    __nv_bfloat16* base = out + orow * K3;
    ((ushort4*)(base))[t]        = hp;
    ((ushort4*)(base + CC))[t]   = mode ? hp : lp;
    ((ushort4*)(base + 2*CC))[t] = mode ? lp : hp;
}

// ---------------------------------------------------------------------------
// Transpose + split-convert: in fp32 [b][256][W] -> out bf16 [b][W][768]
// ---------------------------------------------------------------------------
template<int MODE>
__global__ void trconv_kernel(const float* __restrict__ in, __nv_bfloat16* __restrict__ out, int W)
{
    __shared__ float s[32][33];
    const int b = blockIdx.z;
    const float* ib = in + (long)b * 256 * W;
    __nv_bfloat16* ob = out + (long)b * W * 768;
    const int k0 = blockIdx.y * 32, w0 = blockIdx.x * 32;
    const int tx = threadIdx.x, ty = threadIdx.y;
#pragma unroll
    for (int i = 0; i < 4; i++)
        s[ty + 8*i][tx] = ib[(long)(k0 + ty + 8*i) * W + w0 + tx];
    __syncthreads();
#pragma unroll
    for (int i = 0; i < 4; i++) {
        const int wrow = w0 + ty + 8*i;
        float x = s[tx][ty + 8*i];
        __nv_bfloat16 h, l; split_bf16(x, h, l);
        __nv_bfloat16* p = ob + (long)wrow * 768 + k0 + tx;
        p[0]   = h;
        p[256] = MODE ? h : l;
        p[512] = MODE ? l : h;
    }
}

// ---------------------------------------------------------------------------
// Sinkhorn (validated): one warp per (b,k) problem, scaling-domain.
// ---------------------------------------------------------------------------
__global__ __launch_bounds__(256)
void sinkhorn_kernel(const float* __restrict__ sim, float* __restrict__ T,
                     float* __restrict__ score)
{
    const int p    = blockIdx.x * 8 + (threadIdx.x >> 5);
    const int lane = threadIdx.x & 31;
    const float* srow = sim + (long)p * (MMQ * NQ);

    float Km[32];
#pragma unroll
    for (int i = 0; i < 16; i++) {
        Km[i]      = __expf((srow[i * 64 + lane]      - 1.0f) * INV_EPS);
        Km[i + 16] = __expf((srow[i * 64 + lane + 32] - 1.0f) * INV_EPS);
    }

    const float MU = 1.0f / 16.0f + 1e-8f;
    const float NU = 1.0f / 64.0f + 1e-8f;
    float b0 = 1.0f, b1 = 1.0f;
    float a[16];

#pragma unroll 1
    for (int iter = 0; iter < 100; iter++) {
        float v[16];
#pragma unroll
        for (int i = 0; i < 16; i++) v[i] = Km[i] * b0 + Km[i + 16] * b1;
#pragma unroll
        for (int i = 0; i < 16; i++) v[i] += __shfl_xor_sync(0xffffffffu, v[i], 16);
#pragma unroll
        for (int i = 0; i < 8; i++) {
            float t0 = v[i], t1 = v[i + 8];
            float r0 = __shfl_xor_sync(0xffffffffu, t0, 8);
            float r1 = __shfl_xor_sync(0xffffffffu, t1, 8);
            v[i] = (lane & 8) ? (t1 + r1) : (t0 + r0);
        }
#pragma unroll
        for (int i = 0; i < 4; i++) {
            float t0 = v[i], t1 = v[i + 4];
            float r0 = __shfl_xor_sync(0xffffffffu, t0, 4);
            float r1 = __shfl_xor_sync(0xffffffffu, t1, 4);
            v[i] = (lane & 4) ? (t1 + r1) : (t0 + r0);
        }
#pragma unroll
        for (int i = 0; i < 2; i++) {
            float t0 = v[i], t1 = v[i + 2];
            float r0 = __shfl_xor_sync(0xffffffffu, t0, 2);
            float r1 = __shfl_xor_sync(0xffffffffu, t1, 2);
            v[i] = (lane & 2) ? (t1 + r1) : (t0 + r0);
        }
        {
            float t0 = v[0], t1 = v[1];
            float r0 = __shfl_xor_sync(0xffffffffu, t0, 1);
            float r1 = __shfl_xor_sync(0xffffffffu, t1, 1);
            v[0] = (lane & 1) ? (t1 + r1) : (t0 + r0);
        }
        float av = __fdividef(MU, v[0]);
#pragma unroll
        for (int i = 0; i < 16; i++) a[i] = __shfl_sync(0xffffffffu, av, i);

        float c0a = 0.f, c0b = 0.f, c1a = 0.f, c1b = 0.f;
#pragma unroll
        for (int i = 0; i < 16; i += 2) {
            c0a += Km[i] * a[i];       c0b += Km[i + 1] * a[i + 1];
            c1a += Km[i + 16] * a[i];  c1b += Km[i + 17] * a[i + 1];
        }
        b0 = __fdividef(NU, c0a + c0b);
        b1 = __fdividef(NU, c1a + c1b);
    }

    float* Trow = T + (long)p * (MMQ * NQ);
    float* Srow = score + (long)p * (MMQ * NQ);
#pragma unroll
    for (int i = 0; i < 16; i++) {
        float T0 = a[i] * Km[i] * b0;
        float T1 = a[i] * Km[i + 16] * b1;
        Trow[i * 64 + lane]      = T0;
        Trow[i * 64 + lane + 32] = T1;
        Srow[i * 64 + lane]      = 1024.0f * srow[i * 64 + lane] * T0;
        Srow[i * 64 + lane + 32] = 1024.0f * srow[i * 64 + lane + 32] * T1;
    }
}

// ---------------------------------------------------------------------------
extern "C" void kernel_launch(void* const* d_in, const int* in_sizes, int n_in,
                              void* d_out, int out_size)
{
    const float* xq = (const float*)d_in[0];
    const float* xk = (const float*)d_in[1];
    const float* xv = (const float*)d_in[2];
    const float* Wq = (const float*)d_in[3];
    const float* Wk = (const float*)d_in[4];
    const float* Wv = (const float*)d_in[5];
    const float* Wp = (const float*)d_in[6];
    const float* bp = (const float*)d_in[7];
    float* out_x     = (float*)d_out;
    float* out_score = out_x + X_ELEMS;

    __nv_bfloat16 *xq3,*xk3,*xv3,*wq3,*wk3,*wv3,*wp3,*qr3,*kn3,*Tt3,*vT3,*v3;
    float *qlin,*klin,*vp,*sim,*T;
    cudaGetSymbolAddress((void**)&xq3, g_xq3);
    cudaGetSymbolAddress((void**)&xk3, g_xk3);
    cudaGetSymbolAddress((void**)&xv3, g_xv3);
    cudaGetSymbolAddress((void**)&wq3, g_wq3);
    cudaGetSymbolAddress((void**)&wk3, g_wk3);
    cudaGetSymbolAddress((void**)&wv3, g_wv3);
    cudaGetSymbolAddress((void**)&wp3, g_wp3);
    cudaGetSymbolAddress((void**)&qr3, g_qr3);
    cudaGetSymbolAddress((void**)&kn3, g_kn3);
    cudaGetSymbolAddress((void**)&Tt3, g_Tt3);
    cudaGetSymbolAddress((void**)&vT3, g_vT3);
    cudaGetSymbolAddress((void**)&v3,  g_v3);
    cudaGetSymbolAddress((void**)&qlin, g_qlin);
    cudaGetSymbolAddress((void**)&klin, g_klin);
    cudaGetSymbolAddress((void**)&vp,   g_v);
    cudaGetSymbolAddress((void**)&sim,  g_sim);
    cudaGetSymbolAddress((void**)&T,    g_T);

    cudaFuncSetAttribute(hgemm<0>,   cudaFuncAttributeMaxDynamicSharedMemorySize, GSMEM);
    cudaFuncSetAttribute(hgemm<2>,   cudaFuncAttributeMaxDynamicSharedMemorySize, GSMEM);
    cudaFuncSetAttribute(hgemm<3>,   cudaFuncAttributeMaxDynamicSharedMemorySize, GSMEM);
    cudaFuncSetAttribute(hgemm_proj, cudaFuncAttributeMaxDynamicSharedMemorySize, GSMEM);

    // Side stream + events for fork/join (host objects; graph replays skip host code)
    cudaStream_t sA;
    cudaStreamCreateWithFlags(&sA, cudaStreamNonBlocking);
    cudaEvent_t eRoot, eActs, eProj, eV;
    cudaEventCreateWithFlags(&eRoot, cudaEventDisableTiming);
    cudaEventCreateWithFlags(&eActs, cudaEventDisableTiming);
    cudaEventCreateWithFlags(&eProj, cudaEventDisableTiming);
    cudaEventCreateWithFlags(&eV,    cudaEventDisableTiming);

    // --- fork: weights conv (main) || acts conv (sA) ---
    cudaEventRecord(eRoot, 0);
    conv3_weights<<<4 * CC, 128>>>(Wq, wq3, Wk, wk3, Wv, wv3, Wp, wp3);
    cudaStreamWaitEvent(sA, eRoot, 0);
    conv3_acts<<<12288, 128, 0, sA>>>(xq, xq3, xk, xk3, xv, xv3);
    cudaEventRecord(eActs, sA);
    cudaStreamWaitEvent(0, eActs, 0);

    // --- q/k/v projections: single fused launch (v emits split-bf16) ---
    hgemm_proj<<<dim3(4, 96, 1), 256, GSMEM>>>(
        xq3, wq3, qlin, xk3, wk3, klin, xv3, wv3, v3);
    cudaEventRecord(eProj, 0);

    // --- fork (sA): vp = v·Wp^T, then transpose+split — overlapped with
    //     norm + sim + sinkhorn on main ---
    cudaStreamWaitEvent(sA, eProj, 0);
    hgemm<0><<<dim3(4, 16, 1), 256, GSMEM, sA>>>(
        v3, wp3, vp, nullptr, K3, CC, 0, 0, 0);
    trconv_kernel<1><<<dim3(16, 8, 8), dim3(32, 8), 0, sA>>>(vp, vT3, 512);
    cudaEventRecord(eV, sA);

    // --- main: l2 normalize (fused q+k) ---
    norm_fused<<<NROWS_Q + NROWS_K, 128>>>(qlin, qr3, klin, kn3);

    // --- sim[b][k][m*64+n] (fp32) ---
    hgemm<0><<<dim3(8, 2, 8), 256, GSMEM>>>(
        kn3, qr3, sim, nullptr, K3, 1024,
        (long)256 * K3, (long)1024 * K3, (long)256 * 1024);

    // --- Sinkhorn -> T + score_map ---
    sinkhorn_kernel<<<BKP / 8, 256>>>(sim, T, out_score);

    // --- T transpose ---
    trconv_kernel<0><<<dim3(32, 8, 8), dim3(32, 8)>>>(T, Tt3, 1024);

    // --- join vp path; x = T^T·vp + bp with direct scatter to (n,m,b,c) ---
    cudaStreamWaitEvent(0, eV, 0);
    hgemm<3><<<dim3(4, 8, 8), 256, GSMEM>>>(
        Tt3, vT3, out_x, bp, 768, CC,
        (long)1024 * 768, (long)512 * 768, 0);
}